// round 4
// baseline (speedup 1.0000x reference)
#include <cuda_runtime.h>
#include <cuda_bf16.h>
#include <math.h>
#include <stdint.h>

#define DEV_INLINE __device__ __forceinline__

// Problem constants
constexpr int Bc = 4, Tc = 200, Uc = 100, U1 = 101, Hc = 320, IN = 512, Vc = 1000;
constexpr int ROWS_B = Tc * U1;                    // 20200 rows (t,u) per batch
constexpr int MT = 128;                            // rows per CTA
constexpr int VPAD = 1024;                         // V padded to 8x128
constexpr int BLKS_B = (ROWS_B + MT - 1) / MT;     // 158

constexpr int AS = 520;                            // A smem stride (bf16 elems)
constexpr int BS = 136;                            // B smem stride (bf16 elems), k=128 + pad
constexpr int A_BYTES = MT * AS * 2;               // 133120
constexpr int B_BYTES = 128 * BS * 2;              // 34816
constexpr int DSMEM = A_BYTES + 2 * B_BYTES;       // 202752
constexpr int NSTAGE = 32;                         // 8 ntiles x 4 kchunks(128)

// Scratch (no allocations allowed -> device globals)
__device__ __align__(16) float g_henc[Bc * Tc * IN];
__device__ __align__(16) float g_hdec[Bc * U1 * IN];
__device__ __align__(16) __nv_bfloat16 g_W2t[VPAD * IN];   // W2^T [v][k], bf16
__device__ __align__(16) float g_blank[Bc * Tc * U1];
__device__ __align__(16) float g_label[Bc * Tc * Uc];
__device__ float g_ll[Bc];

// ---------------------------------------------------------------------------
// Helpers
// ---------------------------------------------------------------------------
DEV_INLINE float tanh_approx(float x) {
    float y; asm("tanh.approx.f32 %0, %1;" : "=f"(y) : "f"(x)); return y;
}
DEV_INLINE uint32_t smemu32(const void* p) {
    uint32_t a;
    asm("{ .reg .u64 t; cvta.to.shared.u64 t, %1; cvt.u32.u64 %0, t; }" : "=r"(a) : "l"(p));
    return a;
}
DEV_INLINE void cp_async16(uint32_t dst, const void* src) {
    asm volatile("cp.async.ca.shared.global [%0], [%1], 16;"
                 :: "r"(dst), "l"(src) : "memory");
}
DEV_INLINE void cp_commit() { asm volatile("cp.async.commit_group;" ::: "memory"); }
DEV_INLINE void cp_wait0()  { asm volatile("cp.async.wait_group 0;" ::: "memory"); }

DEV_INLINE void ldmx4(uint32_t addr, uint32_t& r0, uint32_t& r1, uint32_t& r2, uint32_t& r3) {
    asm volatile("ldmatrix.sync.aligned.m8n8.x4.shared.b16 {%0,%1,%2,%3}, [%4];"
                 : "=r"(r0), "=r"(r1), "=r"(r2), "=r"(r3) : "r"(addr));
}
DEV_INLINE void mma_bf16(float& c0, float& c1, float& c2, float& c3,
                         uint32_t a0, uint32_t a1, uint32_t a2, uint32_t a3,
                         uint32_t b0, uint32_t b1) {
    asm volatile(
        "mma.sync.aligned.m16n8k16.row.col.f32.bf16.bf16.f32 "
        "{%0,%1,%2,%3}, {%4,%5,%6,%7}, {%8,%9}, {%0,%1,%2,%3};"
        : "+f"(c0), "+f"(c1), "+f"(c2), "+f"(c3)
        : "r"(a0), "r"(a1), "r"(a2), "r"(a3), "r"(b0), "r"(b1));
}

// ---------------------------------------------------------------------------
// Kernel 0: W2 [512][1000] fp32 -> g_W2t [1024][512] bf16 (transpose + pad 0)
// ---------------------------------------------------------------------------
__global__ __launch_bounds__(256) void w2prep(const float* __restrict__ W2) {
    __shared__ float tile[32][33];
    const int kb = blockIdx.x * 32, vb = blockIdx.y * 32;
    const int tx = threadIdx.x & 31, ty = threadIdx.x >> 5;
#pragma unroll
    for (int i = 0; i < 4; ++i) {
        int k = kb + ty + 8 * i, v = vb + tx;
        tile[ty + 8 * i][tx] = (v < Vc) ? W2[(size_t)k * Vc + v] : 0.f;
    }
    __syncthreads();
#pragma unroll
    for (int i = 0; i < 4; ++i) {
        int v = vb + ty + 8 * i, k = kb + tx;
        g_W2t[(size_t)v * IN + k] = __float2bfloat16(tile[tx][ty + 8 * i]);
    }
}

// ---------------------------------------------------------------------------
// Kernel 1: projections  h_enc = enc @ W1[:H] + b1 ; h_dec = dec @ W1[H:]
// grid (151, 2): 8 rows x 256 cols per block, 2 cols/thread (float2).
// ---------------------------------------------------------------------------
constexpr int ENC_BLKS = (Bc * Tc) / 8;            // 100
constexpr int DEC_BLKS = (Bc * U1 + 7) / 8;        // 51

__global__ __launch_bounds__(128) void proj_kernel(
    const float* __restrict__ enc, const float* __restrict__ dec,
    const float* __restrict__ W1, const float* __restrict__ b1) {
    __shared__ float x_s[8][Hc];
    const int blk = blockIdx.x;
    const bool is_enc = blk < ENC_BLKS;
    const int r0 = (is_enc ? blk : blk - ENC_BLKS) * 8;
    const int nrows = is_enc ? Bc * Tc : Bc * U1;
    const float* __restrict__ X = is_enc ? enc : dec;
    float* __restrict__ Y = is_enc ? g_henc : g_hdec;
    const int woff = is_enc ? 0 : Hc;
    const int col = blockIdx.y * 256 + threadIdx.x * 2;

    for (int idx = threadIdx.x; idx < 8 * Hc; idx += 128) {
        int r = idx / Hc, i = idx - r * Hc;
        x_s[r][i] = (r0 + r < nrows) ? X[(size_t)(r0 + r) * Hc + i] : 0.f;
    }
    __syncthreads();

    float2 acc[8];
    const float2 bv = is_enc ? *(const float2*)&b1[col] : make_float2(0.f, 0.f);
#pragma unroll
    for (int r = 0; r < 8; ++r) acc[r] = bv;
#pragma unroll 4
    for (int h = 0; h < Hc; ++h) {
        float2 w = *(const float2*)&W1[(size_t)(woff + h) * IN + col];
#pragma unroll
        for (int r = 0; r < 8; ++r) {
            float xv = x_s[r][h];
            acc[r].x = fmaf(xv, w.x, acc[r].x);
            acc[r].y = fmaf(xv, w.y, acc[r].y);
        }
    }
#pragma unroll
    for (int r = 0; r < 8; ++r)
        if (r0 + r < nrows) *(float2*)&Y[(size_t)(r0 + r) * IN + col] = acc[r];
}

// ---------------------------------------------------------------------------
// Kernel 2 (dominant): mma.sync bf16 joint GEMM + fused fixed-max logsumexp.
//   A = tanh(henc+hdec) [128 x 512] bf16 (stride 520)
//   B = W2t chunks [128 n x 128 k] bf16, cp.async double-buffered, 1 sync/stage
//   Epilogue per ntile: s += sum exp(logit)   (logits tightly bounded -> max=0)
// 256 threads = 8 warps = 4(m) x 2(n); warp tile 32 x 64.
// ---------------------------------------------------------------------------
__global__ __launch_bounds__(256, 1) void joint_mma(
    const float* __restrict__ b2, const int* __restrict__ tokens) {
    extern __shared__ char dsm[];
    __shared__ __align__(16) float b2s[VPAD];
    __shared__ float cs[2][MT], ctk[2][MT], cbl[MT];

    const int tid = threadIdx.x;
    const int lane = tid & 31, wid = tid >> 5;
    const int warp_m = wid >> 1, warp_n = wid & 1;
    const int qr = lane >> 2, qc = lane & 3;
    const int b = blockIdx.x / BLKS_B;
    const int row0 = (blockIdx.x % BLKS_B) * MT;

    const uint32_t a_base = smemu32(dsm);
    const uint32_t b_base = a_base + A_BYTES;

    // cp.async mapping: thread -> row n = tid>>1, k-half = (tid&1)*64, 8x16B
    const int cp_n = tid >> 1;
    const int cp_k = (tid & 1) * 64;
    const uint32_t cp_dst0 = b_base + (uint32_t)(cp_n * BS + cp_k) * 2;
    const __nv_bfloat16* cp_src0 = g_W2t + (size_t)cp_n * IN + cp_k;

    // prologue: issue B stage 0 (nt=0, kc=0)
#pragma unroll
    for (int q = 0; q < 8; ++q)
        cp_async16(cp_dst0 + q * 16, cp_src0 + q * 8);
    cp_commit();

    for (int i = tid; i < VPAD; i += 256) b2s[i] = (i < Vc) ? b2[i] : -INFINITY;

    // ---- build A tile: h = tanh(henc[t] + hdec[u]) in bf16 ----
#pragma unroll 2
    for (int r = 0; r < MT; ++r) {
        int row = row0 + r;
        float2 hv = make_float2(0.f, 0.f);
        if (row < ROWS_B) {
            int t = row / U1, u = row - t * U1;
            float2 e = ((const float2*)(g_henc + (size_t)(b * Tc + t) * IN))[tid];
            float2 d = ((const float2*)(g_hdec + (size_t)(b * U1 + u) * IN))[tid];
            hv.x = tanh_approx(e.x + d.x);
            hv.y = tanh_approx(e.y + d.y);
        }
        *(__nv_bfloat162*)(dsm + r * (AS * 2) + tid * 4) = __float22bfloat162_rn(hv);
    }

    // per-slot (4 rows/thread) state: sum-of-exp (fixed max 0), blank, token
    float s4[4], tk4[4], bl4[4];
    int rowloc[4], tcol4[4];
#pragma unroll
    for (int s = 0; s < 4; ++s) {
        s4[s] = 0.f; tk4[s] = -INFINITY; bl4[s] = -INFINITY;
        rowloc[s] = warp_m * 32 + (s >> 1) * 16 + (s & 1) * 8 + qr;
        int row = row0 + rowloc[s];
        int u = row % U1;
        tcol4[s] = (row < ROWS_B && u < Uc) ? tokens[b * Uc + u] : -1;
    }

    // ldmatrix lane-address offsets
    const int a_row_off = (lane & 7) + ((lane >> 3) & 1) * 8;
    const int a_k_off = (lane >> 4) * 8;
    const int b_n_off = (lane & 7) + ((lane >> 4) & 1) * 8;
    const int b_k_off = ((lane >> 3) & 1) * 8;
    const uint32_t a_addr0 =
        a_base + (uint32_t)((warp_m * 32 + a_row_off) * AS + a_k_off) * 2;
    const uint32_t b_addr0 =
        b_base + (uint32_t)((warp_n * 64 + b_n_off) * BS + b_k_off) * 2;

    float acc[2][8][4];

    for (int st = 0; st < NSTAGE; ++st) {      // 8 ntiles x 4 kchunks of 128
        const int buf = st & 1;
        const int nt = st >> 2, kc = st & 3;

        cp_wait0();           // current buffer's async group complete
        __syncthreads();      // all threads past reads of the other buffer

        if (st + 1 < NSTAGE) {                 // issue next stage -> other buf
            int nn = (st + 1) >> 2, nk = (st + 1) & 3;
            const __nv_bfloat16* src =
                g_W2t + (size_t)(nn * 128) * IN + nk * 128 + cp_k;
            uint32_t dst = cp_dst0 + ((st + 1) & 1) * B_BYTES;
            const __nv_bfloat16* s0 = src + (size_t)cp_n * 0; // keep simple
#pragma unroll
            for (int q = 0; q < 8; ++q)
                cp_async16(dst + q * 16,
                           g_W2t + (size_t)(nn * 128 + cp_n) * IN + nk * 128 + cp_k + q * 8);
            (void)s0;
            cp_commit();
        }

        if (kc == 0) {
#pragma unroll
            for (int mi = 0; mi < 2; ++mi)
#pragma unroll
                for (int nf = 0; nf < 8; ++nf)
#pragma unroll
                    for (int r = 0; r < 4; ++r) acc[mi][nf][r] = 0.f;
        }

        const uint32_t bb = b_addr0 + buf * B_BYTES;
#pragma unroll
        for (int kk = 0; kk < 128; kk += 16) {
            uint32_t a[2][4], bfrg[4][4];
#pragma unroll
            for (int mi = 0; mi < 2; ++mi)
                ldmx4(a_addr0 + (uint32_t)(mi * 16 * AS + kc * 128 + kk) * 2,
                      a[mi][0], a[mi][1], a[mi][2], a[mi][3]);
#pragma unroll
            for (int ng = 0; ng < 4; ++ng)
                ldmx4(bb + (uint32_t)(ng * 16 * BS + kk) * 2,
                      bfrg[ng][0], bfrg[ng][1], bfrg[ng][2], bfrg[ng][3]);
#pragma unroll
            for (int mi = 0; mi < 2; ++mi)
#pragma unroll
                for (int nf = 0; nf < 8; ++nf) {
                    int ng = nf >> 1, pr = (nf & 1) * 2;
                    mma_bf16(acc[mi][nf][0], acc[mi][nf][1],
                             acc[mi][nf][2], acc[mi][nf][3],
                             a[mi][0], a[mi][1], a[mi][2], a[mi][3],
                             bfrg[ng][pr], bfrg[ng][pr + 1]);
                }
        }

        if (kc == 3) {
            // ---- epilogue for n-tile nt: accumulate sum(exp(logit)) ----
            const int gbase = nt * 128 + warp_n * 64;
            float2 eb[8];
#pragma unroll
            for (int nf = 0; nf < 8; ++nf)
                eb[nf] = *(const float2*)&b2s[gbase + nf * 8 + qc * 2];
#pragma unroll
            for (int s = 0; s < 4; ++s) {
                const int mi = s >> 1, hf = (s & 1) * 2;
                float add = 0.f;
#pragma unroll
                for (int nf = 0; nf < 8; ++nf) {
                    float v0 = acc[mi][nf][hf] + eb[nf].x;
                    float v1 = acc[mi][nf][hf + 1] + eb[nf].y;
                    add += __expf(v0) + __expf(v1);
                }
                s4[s] += add;
                if (nt == 0 && warp_n == 0 && qc == 0)
                    bl4[s] = acc[mi][0][hf] + eb[0].x;
                int rel = tcol4[s] - gbase;
                if (rel >= 0 && rel < 64 && ((rel & 7) >> 1) == qc) {
                    int nf = rel >> 3, j = rel & 1;
                    tk4[s] = acc[mi][nf][hf + j] + (j ? eb[nf].y : eb[nf].x);
                }
            }
        }
    }

    // quad reduction (lanes sharing a row): plain sums / maxes
#pragma unroll
    for (int off = 1; off <= 2; off <<= 1) {
#pragma unroll
        for (int s = 0; s < 4; ++s) {
            s4[s] += __shfl_xor_sync(0xffffffffu, s4[s], off);
            tk4[s] = fmaxf(tk4[s], __shfl_xor_sync(0xffffffffu, tk4[s], off));
            bl4[s] = fmaxf(bl4[s], __shfl_xor_sync(0xffffffffu, bl4[s], off));
        }
    }
    if (qc == 0) {
#pragma unroll
        for (int s = 0; s < 4; ++s) {
            int r = rowloc[s];
            cs[warp_n][r] = s4[s];
            ctk[warp_n][r] = tk4[s];
            if (warp_n == 0) cbl[r] = bl4[s];
        }
    }
    __syncthreads();

    if (tid < MT) {
        int row = row0 + tid;
        if (row < ROWS_B) {
            float lse = __logf(cs[0][tid] + cs[1][tid]);
            float tk = fmaxf(ctk[0][tid], ctk[1][tid]);
            int t = row / U1, u = row - t * U1;
            g_blank[(b * Tc + t) * U1 + u] = cbl[tid] - lse;
            if (u < Uc) g_label[(b * Tc + t) * Uc + u] = tk - lse;
        }
    }
}

// ---------------------------------------------------------------------------
// Kernel 3: RNN-T forward DP. One block per batch; lp staged in SMEM; the
// wavefront runs in ONE warp with alpha in registers (4 u per lane), the only
// cross-lane dependency is a single shfl_up per diagonal. No __syncthreads.
// ---------------------------------------------------------------------------
constexpr int DP_SMEM = (Tc * U1 + Tc * Uc) * (int)sizeof(float); // 160800

__global__ __launch_bounds__(128) void dp_kernel(
    const int* __restrict__ out_len, const int* __restrict__ tok_len) {
    extern __shared__ float lp[];
    float* blankS = lp;                 // Tc*U1
    float* labelS = lp + Tc * U1;       // Tc*Uc
    __shared__ float llk;

    const int b = blockIdx.x, tid = threadIdx.x;
    // stage (vectorized: counts divisible by 4, bases 16B aligned)
    {
        const float4* src = (const float4*)(g_blank + (size_t)b * Tc * U1);
        float4* dst = (float4*)blankS;
        for (int i = tid; i < Tc * U1 / 4; i += 128) dst[i] = src[i];
        const float4* src2 = (const float4*)(g_label + (size_t)b * Tc * Uc);
        float4* dst2 = (float4*)labelS;
        for (int i = tid; i < Tc * Uc / 4; i += 128) dst2[i] = src2[i];
    }
    const int tl = out_len[b], ul = tok_len[b];
    __syncthreads();

    if (tid < 32) {
        const int lane = tid;
        float a[4];
#pragma unroll
        for (int j = 0; j < 4; ++j)
            a[j] = (lane == 0 && j == 0) ? 0.f : -INFINITY;   // alpha[0][0]=0

        for (int d = 1; d <= (Tc - 1) + Uc; ++d) {
            float up = __shfl_up_sync(0xffffffffu, a[3], 1);
            float na[4];
#pragma unroll
            for (int j = 0; j < 4; ++j) {
                int u = lane * 4 + j;
                int t = d - u;
                bool cell = (u <= Uc) & (t >= 0) & (t < Tc);
                float left = (j == 0) ? up : a[j - 1];
                float x = -INFINITY, y = -INFINITY;
                if (cell && t >= 1) x = a[j] + blankS[(t - 1) * U1 + u];
                if (cell && u >= 1) y = left + labelS[t * Uc + (u - 1)];
                float hi = fmaxf(x, y), lo = fminf(x, y);
                float v = (lo == -INFINITY) ? hi
                          : hi + __logf(1.f + __expf(lo - hi));
                na[j] = cell ? v : -INFINITY;
                if (cell && t == tl - 1 && u == ul) llk = v;
            }
#pragma unroll
            for (int j = 0; j < 4; ++j) a[j] = na[j];
        }
        __syncwarp();
        if (lane == 0) g_ll[b] = llk + blankS[(tl - 1) * U1 + ul];
    }
}

__global__ void finalize_kernel(float* out) {
    out[0] = -0.25f * (g_ll[0] + g_ll[1] + g_ll[2] + g_ll[3]);
}

// ---------------------------------------------------------------------------
extern "C" void kernel_launch(void* const* d_in, const int* in_sizes, int n_in,
                              void* d_out, int out_size) {
    const float* enc     = (const float*)d_in[0];
    const float* dec     = (const float*)d_in[1];
    const int*   tokens  = (const int*)d_in[2];
    const int*   out_len = (const int*)d_in[3];
    const int*   tok_len = (const int*)d_in[4];
    const float* W1      = (const float*)d_in[5];
    const float* b1      = (const float*)d_in[6];
    const float* W2      = (const float*)d_in[7];
    const float* b2      = (const float*)d_in[8];
    float* out = (float*)d_out;

    cudaFuncSetAttribute(joint_mma, cudaFuncAttributeMaxDynamicSharedMemorySize, DSMEM);
    cudaFuncSetAttribute(dp_kernel, cudaFuncAttributeMaxDynamicSharedMemorySize, DP_SMEM);

    w2prep<<<dim3(IN / 32, VPAD / 32), 256>>>(W2);
    proj_kernel<<<dim3(ENC_BLKS + DEC_BLKS, 2), 128>>>(enc, dec, W1, b1);
    joint_mma<<<Bc * BLKS_B, 256, DSMEM>>>(b2, tokens);
    dp_kernel<<<Bc, 128, DP_SMEM>>>(out_len, tok_len);
    finalize_kernel<<<1, 1>>>(out);
}

// round 5
// speedup vs baseline: 1.4835x; 1.4835x over previous
#include <cuda_runtime.h>
#include <cuda_bf16.h>
#include <math.h>
#include <stdint.h>

#define DEV_INLINE __device__ __forceinline__

// Problem constants
constexpr int Bc = 4, Tc = 200, Uc = 100, U1 = 101, Hc = 320, IN = 512, Vc = 1000;
constexpr int ROWS_B = Tc * U1;                    // 20200 rows (t,u) per batch
constexpr int MT = 128;                            // rows per CTA
constexpr int VPAD = 1024;                         // V padded to 8x128
constexpr int BLKS_B = (ROWS_B + MT - 1) / MT;     // 158

constexpr int AS = 520;                            // A smem stride (bf16 elems)
constexpr int BS = 72;                             // B smem stride (bf16 elems)
constexpr int A_BYTES = MT * AS * 2;               // 133120
constexpr int B_BYTES = 128 * BS * 2;              // 18432
constexpr int NBUF = 3;
constexpr int DSMEM = A_BYTES + NBUF * B_BYTES;    // 188416
constexpr int NCHUNK = 64;                         // 8 ntiles x 8 kchunks(64)

// Scratch (no allocations allowed -> device globals)
__device__ __align__(16) float g_henc[Bc * Tc * IN];
__device__ __align__(16) float g_hdec[Bc * U1 * IN];
__device__ __align__(16) __nv_bfloat16 g_W2t[VPAD * IN];   // W2^T [v][k], bf16
__device__ __align__(16) float g_blank[Bc * Tc * U1];
__device__ __align__(16) float g_label[Bc * Tc * Uc];
__device__ float g_ll[Bc];

// ---------------------------------------------------------------------------
// Helpers
// ---------------------------------------------------------------------------
DEV_INLINE float tanh_approx(float x) {
    float y; asm("tanh.approx.f32 %0, %1;" : "=f"(y) : "f"(x)); return y;
}
DEV_INLINE uint32_t smemu32(const void* p) {
    uint32_t a;
    asm("{ .reg .u64 t; cvta.to.shared.u64 t, %1; cvt.u32.u64 %0, t; }" : "=r"(a) : "l"(p));
    return a;
}
DEV_INLINE void cp_async16(uint32_t dst, const void* src) {
    asm volatile("cp.async.ca.shared.global [%0], [%1], 16;"
                 :: "r"(dst), "l"(src) : "memory");
}
DEV_INLINE void cp_commit() { asm volatile("cp.async.commit_group;" ::: "memory"); }
DEV_INLINE void cp_wait1()  { asm volatile("cp.async.wait_group 1;" ::: "memory"); }
DEV_INLINE void cp_wait0()  { asm volatile("cp.async.wait_group 0;" ::: "memory"); }

DEV_INLINE void ldmx4(uint32_t addr, uint32_t& r0, uint32_t& r1, uint32_t& r2, uint32_t& r3) {
    asm volatile("ldmatrix.sync.aligned.m8n8.x4.shared.b16 {%0,%1,%2,%3}, [%4];"
                 : "=r"(r0), "=r"(r1), "=r"(r2), "=r"(r3) : "r"(addr));
}
DEV_INLINE void mma_bf16(float& c0, float& c1, float& c2, float& c3,
                         uint32_t a0, uint32_t a1, uint32_t a2, uint32_t a3,
                         uint32_t b0, uint32_t b1) {
    asm volatile(
        "mma.sync.aligned.m16n8k16.row.col.f32.bf16.bf16.f32 "
        "{%0,%1,%2,%3}, {%4,%5,%6,%7}, {%8,%9}, {%0,%1,%2,%3};"
        : "+f"(c0), "+f"(c1), "+f"(c2), "+f"(c3)
        : "r"(a0), "r"(a1), "r"(a2), "r"(a3), "r"(b0), "r"(b1));
}

// ---------------------------------------------------------------------------
// Kernel 0: W2 [512][1000] fp32 -> g_W2t [1024][512] bf16 (transpose + pad 0)
// ---------------------------------------------------------------------------
__global__ __launch_bounds__(256) void w2prep(const float* __restrict__ W2) {
    __shared__ float tile[32][33];
    const int kb = blockIdx.x * 32, vb = blockIdx.y * 32;
    const int tx = threadIdx.x & 31, ty = threadIdx.x >> 5;
#pragma unroll
    for (int i = 0; i < 4; ++i) {
        int k = kb + ty + 8 * i, v = vb + tx;
        tile[ty + 8 * i][tx] = (v < Vc) ? W2[(size_t)k * Vc + v] : 0.f;
    }
    __syncthreads();
#pragma unroll
    for (int i = 0; i < 4; ++i) {
        int v = vb + ty + 8 * i, k = kb + tx;
        g_W2t[(size_t)v * IN + k] = __float2bfloat16(tile[tx][ty + 8 * i]);
    }
}

// ---------------------------------------------------------------------------
// Kernel 1: projections  h_enc = enc @ W1[:H] + b1 ; h_dec = dec @ W1[H:]
// grid (151, 4): 8 rows x 128 cols per block, 1 col/thread.
// ---------------------------------------------------------------------------
constexpr int ENC_BLKS = (Bc * Tc) / 8;            // 100
constexpr int DEC_BLKS = (Bc * U1 + 7) / 8;        // 51

__global__ __launch_bounds__(128) void proj_kernel(
    const float* __restrict__ enc, const float* __restrict__ dec,
    const float* __restrict__ W1, const float* __restrict__ b1) {
    __shared__ float x_s[8][Hc];
    const int blk = blockIdx.x;
    const bool is_enc = blk < ENC_BLKS;
    const int r0 = (is_enc ? blk : blk - ENC_BLKS) * 8;
    const int nrows = is_enc ? Bc * Tc : Bc * U1;
    const float* __restrict__ X = is_enc ? enc : dec;
    float* __restrict__ Y = is_enc ? g_henc : g_hdec;
    const int woff = is_enc ? 0 : Hc;
    const int col = blockIdx.y * 128 + threadIdx.x;

    for (int idx = threadIdx.x; idx < 8 * Hc; idx += 128) {
        int r = idx / Hc, i = idx - r * Hc;
        x_s[r][i] = (r0 + r < nrows) ? X[(size_t)(r0 + r) * Hc + i] : 0.f;
    }
    __syncthreads();

    float acc[8];
    const float bv = is_enc ? b1[col] : 0.f;
#pragma unroll
    for (int r = 0; r < 8; ++r) acc[r] = bv;
#pragma unroll 4
    for (int h = 0; h < Hc; ++h) {
        float w = W1[(size_t)(woff + h) * IN + col];
#pragma unroll
        for (int r = 0; r < 8; ++r) acc[r] = fmaf(x_s[r][h], w, acc[r]);
    }
#pragma unroll
    for (int r = 0; r < 8; ++r)
        if (r0 + r < nrows) Y[(size_t)(r0 + r) * IN + col] = acc[r];
}

// ---------------------------------------------------------------------------
// Kernel 2 (dominant): mma.sync bf16 joint GEMM + fused fixed-max logsumexp.
//   A = tanh(henc+hdec) [128 x 512] bf16 (stride 520)
//   B = W2t chunks [128 n x 64 k] bf16, cp.async TRIPLE-buffered, issue 2
//       chunks ahead, ONE __syncthreads per chunk.
//   Epilogue per ntile: s += sum exp(logit) (logits tightly bounded; max=0).
//   NO dynamic indexing of acc (avoids local-memory spill of accumulators).
// 256 threads = 8 warps = 4(m) x 2(n); warp tile 32 x 64.
// ---------------------------------------------------------------------------
__global__ __launch_bounds__(256, 1) void joint_mma(
    const float* __restrict__ b2, const int* __restrict__ tokens) {
    extern __shared__ char dsm[];
    __shared__ __align__(16) float b2s[VPAD];
    __shared__ float cs[2][MT], ctk[2][MT], cbl[MT];

    const int tid = threadIdx.x;
    const int lane = tid & 31, wid = tid >> 5;
    const int warp_m = wid >> 1, warp_n = wid & 1;
    const int qr = lane >> 2, qc = lane & 3;
    const int b = blockIdx.x / BLKS_B;
    const int row0 = (blockIdx.x % BLKS_B) * MT;

    const uint32_t a_base = smemu32(dsm);
    const uint32_t b_base = a_base + A_BYTES;

    // cp.async mapping: i = tid*4+q -> row n = i>>3, k-16B-slot = (i&7)*8
    const int cp_n0 = (tid * 4) >> 3;       // rows tid/2*... (two threads/row pairing)
    // prologue: issue chunks 0 and 1
#pragma unroll
    for (int c0 = 0; c0 < 2; ++c0) {
        const __nv_bfloat16* src = g_W2t + (size_t)0 * IN + c0 * 64;
        uint32_t dst = b_base + c0 * B_BYTES;
#pragma unroll
        for (int q = 0; q < 4; ++q) {
            int i = tid * 4 + q;
            int n = i >> 3, kk8 = (i & 7) * 8;
            cp_async16(dst + (uint32_t)(n * BS + kk8) * 2,
                       src + (size_t)n * IN + kk8);
        }
        cp_commit();
    }
    (void)cp_n0;

    for (int i = tid; i < VPAD; i += 256) b2s[i] = (i < Vc) ? b2[i] : -INFINITY;

    // ---- build A tile: h = tanh(henc[t] + hdec[u]) in bf16 ----
#pragma unroll 2
    for (int r = 0; r < MT; ++r) {
        int row = row0 + r;
        float2 hv = make_float2(0.f, 0.f);
        if (row < ROWS_B) {
            int t = row / U1, u = row - t * U1;
            float2 e = ((const float2*)(g_henc + (size_t)(b * Tc + t) * IN))[tid];
            float2 d = ((const float2*)(g_hdec + (size_t)(b * U1 + u) * IN))[tid];
            hv.x = tanh_approx(e.x + d.x);
            hv.y = tanh_approx(e.y + d.y);
        }
        *(__nv_bfloat162*)(dsm + r * (AS * 2) + tid * 4) = __float22bfloat162_rn(hv);
    }

    // per-slot (4 rows/thread) state
    float s4[4], tk4[4], bl4[4];
    int rowloc[4], tcol4[4];
#pragma unroll
    for (int s = 0; s < 4; ++s) {
        s4[s] = 0.f; tk4[s] = -INFINITY; bl4[s] = -INFINITY;
        rowloc[s] = warp_m * 32 + (s >> 1) * 16 + (s & 1) * 8 + qr;
        int row = row0 + rowloc[s];
        int u = row % U1;
        tcol4[s] = (row < ROWS_B && u < Uc) ? tokens[b * Uc + u] : -1;
    }

    // ldmatrix lane-address offsets
    const int a_row_off = (lane & 7) + ((lane >> 3) & 1) * 8;
    const int a_k_off = (lane >> 4) * 8;
    const int b_n_off = (lane & 7) + ((lane >> 4) & 1) * 8;
    const int b_k_off = ((lane >> 3) & 1) * 8;
    const uint32_t a_addr0 =
        a_base + (uint32_t)((warp_m * 32 + a_row_off) * AS + a_k_off) * 2;
    const uint32_t b_addr0 =
        b_base + (uint32_t)((warp_n * 64 + b_n_off) * BS + b_k_off) * 2;

    float acc[2][8][4];
    int bufc = 0, bufp2 = 2;   // ch%3, (ch+2)%3

    for (int ch = 0; ch < NCHUNK; ++ch) {   // 8 ntiles x 8 kchunks of 64
        const int nt = ch >> 3, kc = ch & 7;

        if (ch == NCHUNK - 1) cp_wait0(); else cp_wait1();
        __syncthreads();      // cp visibility + all reads of target buf done

        if (ch + 2 < NCHUNK) {             // issue chunk ch+2 -> buf (ch+2)%3
            int nn = (ch + 2) >> 3, nk = (ch + 2) & 7;
            const __nv_bfloat16* src = g_W2t + (size_t)(nn * 128) * IN + nk * 64;
            uint32_t dst = b_base + bufp2 * B_BYTES;
#pragma unroll
            for (int q = 0; q < 4; ++q) {
                int i = tid * 4 + q;
                int n = i >> 3, kk8 = (i & 7) * 8;
                cp_async16(dst + (uint32_t)(n * BS + kk8) * 2,
                           src + (size_t)n * IN + kk8);
            }
            cp_commit();
        }

        if (kc == 0) {
#pragma unroll
            for (int mi = 0; mi < 2; ++mi)
#pragma unroll
                for (int nf = 0; nf < 8; ++nf)
#pragma unroll
                    for (int r = 0; r < 4; ++r) acc[mi][nf][r] = 0.f;
        }

        const uint32_t bb = b_addr0 + bufc * B_BYTES;
#pragma unroll
        for (int kk = 0; kk < 64; kk += 16) {
            uint32_t a[2][4], bfrg[4][4];
#pragma unroll
            for (int mi = 0; mi < 2; ++mi)
                ldmx4(a_addr0 + (uint32_t)(mi * 16 * AS + kc * 64 + kk) * 2,
                      a[mi][0], a[mi][1], a[mi][2], a[mi][3]);
#pragma unroll
            for (int ng = 0; ng < 4; ++ng)
                ldmx4(bb + (uint32_t)(ng * 16 * BS + kk) * 2,
                      bfrg[ng][0], bfrg[ng][1], bfrg[ng][2], bfrg[ng][3]);
#pragma unroll
            for (int mi = 0; mi < 2; ++mi)
#pragma unroll
                for (int nf = 0; nf < 8; ++nf) {
                    int ng = nf >> 1, pr = (nf & 1) * 2;
                    mma_bf16(acc[mi][nf][0], acc[mi][nf][1],
                             acc[mi][nf][2], acc[mi][nf][3],
                             a[mi][0], a[mi][1], a[mi][2], a[mi][3],
                             bfrg[ng][pr], bfrg[ng][pr + 1]);
                }
        }

        if (kc == 7) {
            // ---- epilogue for n-tile nt: s += sum exp(logit); fully static
            //      indexing (no dynamic acc access -> no spills). ----
            const int gbase = nt * 128 + warp_n * 64;
#pragma unroll
            for (int s = 0; s < 4; ++s) {
                const int mi = s >> 1, hf = (s & 1) * 2;
                float add = 0.f;
#pragma unroll
                for (int nf = 0; nf < 8; ++nf) {
#pragma unroll
                    for (int j = 0; j < 2; ++j) {
                        int colg = gbase + nf * 8 + qc * 2 + j;
                        float lv = acc[mi][nf][hf + j] + b2s[colg];
                        add += __expf(lv);
                        if (colg == tcol4[s]) tk4[s] = lv;
                    }
                }
                s4[s] += add;
                if (nt == 0 && warp_n == 0 && qc == 0)
                    bl4[s] = acc[mi][0][hf] + b2s[0];
            }
        }
        bufc = (bufc == 2) ? 0 : bufc + 1;
        bufp2 = (bufp2 == 2) ? 0 : bufp2 + 1;
    }

    // quad reduction (lanes sharing a row)
#pragma unroll
    for (int off = 1; off <= 2; off <<= 1) {
#pragma unroll
        for (int s = 0; s < 4; ++s) {
            s4[s] += __shfl_xor_sync(0xffffffffu, s4[s], off);
            tk4[s] = fmaxf(tk4[s], __shfl_xor_sync(0xffffffffu, tk4[s], off));
            bl4[s] = fmaxf(bl4[s], __shfl_xor_sync(0xffffffffu, bl4[s], off));
        }
    }
    if (qc == 0) {
#pragma unroll
        for (int s = 0; s < 4; ++s) {
            int r = rowloc[s];
            cs[warp_n][r] = s4[s];
            ctk[warp_n][r] = tk4[s];
            if (warp_n == 0) cbl[r] = bl4[s];
        }
    }
    __syncthreads();

    if (tid < MT) {
        int row = row0 + tid;
        if (row < ROWS_B) {
            float lse = __logf(cs[0][tid] + cs[1][tid]);
            float tk = fmaxf(ctk[0][tid], ctk[1][tid]);
            int t = row / U1, u = row - t * U1;
            g_blank[(b * Tc + t) * U1 + u] = cbl[tid] - lse;
            if (u < Uc) g_label[(b * Tc + t) * Uc + u] = tk - lse;
        }
    }
}

// ---------------------------------------------------------------------------
// Kernel 3: RNN-T forward DP. One block/batch; lp staged in SMEM; wavefront
// in one warp (4 u per lane, alpha in registers), software-pipelined: next
// diagonal's lp loads are issued before the current diagonal's MUFU chain.
// Guarded loads return -INF so no cell predicate is needed.
// ---------------------------------------------------------------------------
constexpr int DP_SMEM = (Tc * U1 + Tc * Uc) * (int)sizeof(float); // 160800

__global__ __launch_bounds__(128) void dp_kernel(
    const int* __restrict__ out_len, const int* __restrict__ tok_len) {
    extern __shared__ float lp[];
    float* blankS = lp;                 // Tc*U1
    float* labelS = lp + Tc * U1;       // Tc*Uc

    const int b = blockIdx.x, tid = threadIdx.x;
    {
        const float4* src = (const float4*)(g_blank + (size_t)b * Tc * U1);
        float4* dst = (float4*)blankS;
        for (int i = tid; i < Tc * U1 / 4; i += 128) dst[i] = src[i];
        const float4* src2 = (const float4*)(g_label + (size_t)b * Tc * Uc);
        float4* dst2 = (float4*)labelS;
        for (int i = tid; i < Tc * Uc / 4; i += 128) dst2[i] = src2[i];
    }
    const int tl = out_len[b], ul = tok_len[b];
    __syncthreads();
    if (tid >= 32) return;

    const int lane = tid;
    const int u0 = lane * 4;
    const int dstar = tl - 1 + ul;
    const int lstar = ul >> 2, jstar = ul & 3;

    float a0 = (lane == 0) ? 0.f : -INFINITY;     // alpha[0][0] = 0
    float a1 = -INFINITY, a2 = -INFINITY, a3 = -INFINITY;
    float ll = 0.f;

    // guarded diagonal loads: cb[j]=blank[t-1][u], cl[j]=label[t][u-1], t=d-u
    auto loadd = [&](int d, float* cb, float* cl) {
#pragma unroll
        for (int j = 0; j < 4; ++j) {
            int u = u0 + j, t = d - u;
            bool vb = (t >= 1) & (t < Tc) & (u <= Uc);
            bool vl = (t >= 0) & (t < Tc) & (u >= 1) & (u <= Uc);
            cb[j] = vb ? blankS[(t - 1) * U1 + u] : -INFINITY;
            cl[j] = vl ? labelS[t * Uc + (u - 1)] : -INFINITY;
        }
    };

    float cb[4], cl[4];
    loadd(1, cb, cl);

    for (int d = 1; d <= (Tc - 1) + Uc; ++d) {
        float nb[4], nl[4];
        loadd(d + 1, nb, nl);                        // prefetch (independent)
        float up = __shfl_up_sync(0xffffffffu, a3, 1);
        float x0 = a0 + cb[0], y0 = up + cl[0];
        float x1 = a1 + cb[1], y1 = a0 + cl[1];
        float x2 = a2 + cb[2], y2 = a1 + cl[2];
        float x3 = a3 + cb[3], y3 = a2 + cl[3];
        {
            float h = fmaxf(x0, y0), l = fminf(x0, y0);
            a0 = (l == -INFINITY) ? h : h + __logf(1.f + __expf(l - h));
        }
        {
            float h = fmaxf(x1, y1), l = fminf(x1, y1);
            a1 = (l == -INFINITY) ? h : h + __logf(1.f + __expf(l - h));
        }
        {
            float h = fmaxf(x2, y2), l = fminf(x2, y2);
            a2 = (l == -INFINITY) ? h : h + __logf(1.f + __expf(l - h));
        }
        {
            float h = fmaxf(x3, y3), l = fminf(x3, y3);
            a3 = (l == -INFINITY) ? h : h + __logf(1.f + __expf(l - h));
        }
        if (d == dstar && lane == lstar) {
            float av = (jstar == 0) ? a0 : (jstar == 1) ? a1
                      : (jstar == 2) ? a2 : a3;
            ll = av;
        }
#pragma unroll
        for (int j = 0; j < 4; ++j) { cb[j] = nb[j]; cl[j] = nl[j]; }
    }
    if (lane == lstar)
        g_ll[b] = ll + blankS[(tl - 1) * U1 + ul];
}

__global__ void finalize_kernel(float* out) {
    out[0] = -0.25f * (g_ll[0] + g_ll[1] + g_ll[2] + g_ll[3]);
}

// ---------------------------------------------------------------------------
extern "C" void kernel_launch(void* const* d_in, const int* in_sizes, int n_in,
                              void* d_out, int out_size) {
    const float* enc     = (const float*)d_in[0];
    const float* dec     = (const float*)d_in[1];
    const int*   tokens  = (const int*)d_in[2];
    const int*   out_len = (const int*)d_in[3];
    const int*   tok_len = (const int*)d_in[4];
    const float* W1      = (const float*)d_in[5];
    const float* b1      = (const float*)d_in[6];
    const float* W2      = (const float*)d_in[7];
    const float* b2      = (const float*)d_in[8];
    float* out = (float*)d_out;

    cudaFuncSetAttribute(joint_mma, cudaFuncAttributeMaxDynamicSharedMemorySize, DSMEM);
    cudaFuncSetAttribute(dp_kernel, cudaFuncAttributeMaxDynamicSharedMemorySize, DP_SMEM);

    w2prep<<<dim3(IN / 32, VPAD / 32), 256>>>(W2);
    proj_kernel<<<dim3(ENC_BLKS + DEC_BLKS, 4), 128>>>(enc, dec, W1, b1);
    joint_mma<<<Bc * BLKS_B, 256, DSMEM>>>(b2, tokens);
    dp_kernel<<<Bc, 128, DP_SMEM>>>(out_len, tok_len);
    finalize_kernel<<<1, 1>>>(out);
}

// round 6
// speedup vs baseline: 1.5082x; 1.0167x over previous
#include <cuda_runtime.h>
#include <cuda_bf16.h>
#include <math.h>
#include <stdint.h>

#define DEV_INLINE __device__ __forceinline__

// Problem constants
constexpr int Bc = 4, Tc = 200, Uc = 100, U1 = 101, Hc = 320, IN = 512, Vc = 1000;
constexpr int ROWS_B = Tc * U1;                    // 20200 rows (t,u) per batch
constexpr int MT = 64;                             // rows per CTA
constexpr int VPAD = 1024;                         // V padded to 8x128
constexpr int BLKS_B = (ROWS_B + MT - 1) / MT;     // 316

constexpr int AS = 520;                            // A smem stride (bf16 elems)
constexpr int BS = 72;                             // B smem stride (bf16 elems)
constexpr int A_BYTES = MT * AS * 2;               // 66560
constexpr int B_BYTES = 128 * BS * 2;              // 18432
constexpr int DSMEM = A_BYTES + 2 * B_BYTES;       // 103424 -> 2 CTAs/SM
constexpr int NCHUNK = 64;                         // 8 ntiles x 8 kchunks(64)

// Scratch (no allocations allowed -> device globals)
__device__ __align__(16) float g_henc[Bc * Tc * IN];
__device__ __align__(16) float g_hdec[Bc * U1 * IN];
__device__ __align__(16) __nv_bfloat16 g_W2t[VPAD * IN];   // W2^T [v][k], bf16
__device__ __align__(16) float g_blank[Bc * Tc * U1];
__device__ __align__(16) float g_label[Bc * Tc * Uc];
__device__ float g_ll[Bc];

// ---------------------------------------------------------------------------
// Helpers
// ---------------------------------------------------------------------------
DEV_INLINE float tanh_approx(float x) {
    float y; asm("tanh.approx.f32 %0, %1;" : "=f"(y) : "f"(x)); return y;
}
DEV_INLINE uint32_t smemu32(const void* p) {
    uint32_t a;
    asm("{ .reg .u64 t; cvta.to.shared.u64 t, %1; cvt.u32.u64 %0, t; }" : "=r"(a) : "l"(p));
    return a;
}
DEV_INLINE void cp_async16(uint32_t dst, const void* src) {
    asm volatile("cp.async.ca.shared.global [%0], [%1], 16;"
                 :: "r"(dst), "l"(src) : "memory");
}
DEV_INLINE void cp_commit() { asm volatile("cp.async.commit_group;" ::: "memory"); }
DEV_INLINE void cp_wait0()  { asm volatile("cp.async.wait_group 0;" ::: "memory"); }

DEV_INLINE void ldmx4(uint32_t addr, uint32_t& r0, uint32_t& r1, uint32_t& r2, uint32_t& r3) {
    asm volatile("ldmatrix.sync.aligned.m8n8.x4.shared.b16 {%0,%1,%2,%3}, [%4];"
                 : "=r"(r0), "=r"(r1), "=r"(r2), "=r"(r3) : "r"(addr));
}
DEV_INLINE void mma_bf16(float& c0, float& c1, float& c2, float& c3,
                         uint32_t a0, uint32_t a1, uint32_t a2, uint32_t a3,
                         uint32_t b0, uint32_t b1) {
    asm volatile(
        "mma.sync.aligned.m16n8k16.row.col.f32.bf16.bf16.f32 "
        "{%0,%1,%2,%3}, {%4,%5,%6,%7}, {%8,%9}, {%0,%1,%2,%3};"
        : "+f"(c0), "+f"(c1), "+f"(c2), "+f"(c3)
        : "r"(a0), "r"(a1), "r"(a2), "r"(a3), "r"(b0), "r"(b1));
}

// ---------------------------------------------------------------------------
// Kernel 0: W2 [512][1000] fp32 -> g_W2t [1024][512] bf16 (transpose + pad 0)
// ---------------------------------------------------------------------------
__global__ __launch_bounds__(256) void w2prep(const float* __restrict__ W2) {
    __shared__ float tile[32][33];
    const int kb = blockIdx.x * 32, vb = blockIdx.y * 32;
    const int tx = threadIdx.x & 31, ty = threadIdx.x >> 5;
#pragma unroll
    for (int i = 0; i < 4; ++i) {
        int k = kb + ty + 8 * i, v = vb + tx;
        tile[ty + 8 * i][tx] = (v < Vc) ? W2[(size_t)k * Vc + v] : 0.f;
    }
    __syncthreads();
#pragma unroll
    for (int i = 0; i < 4; ++i) {
        int v = vb + ty + 8 * i, k = kb + tx;
        g_W2t[(size_t)v * IN + k] = __float2bfloat16(tile[tx][ty + 8 * i]);
    }
}

// ---------------------------------------------------------------------------
// Kernel 1: projections  h_enc = enc @ W1[:H] + b1 ; h_dec = dec @ W1[H:]
// 4 rows x 128 cols per block; grid (301, 4) = 1204 blocks (latency hidden).
// ---------------------------------------------------------------------------
constexpr int ENC_BLKS = (Bc * Tc) / 4;            // 200
constexpr int DEC_BLKS = (Bc * U1) / 4;            // 101

__global__ __launch_bounds__(128) void proj_kernel(
    const float* __restrict__ enc, const float* __restrict__ dec,
    const float* __restrict__ W1, const float* __restrict__ b1) {
    __shared__ float x_s[4][Hc];
    const int blk = blockIdx.x;
    const bool is_enc = blk < ENC_BLKS;
    const int r0 = (is_enc ? blk : blk - ENC_BLKS) * 4;
    const float* __restrict__ X = is_enc ? enc : dec;
    float* __restrict__ Y = is_enc ? g_henc : g_hdec;
    const int woff = is_enc ? 0 : Hc;
    const int col = blockIdx.y * 128 + threadIdx.x;

    for (int idx = threadIdx.x; idx < 4 * Hc; idx += 128) {
        int r = idx / Hc, i = idx - r * Hc;
        x_s[r][i] = X[(size_t)(r0 + r) * Hc + i];
    }
    __syncthreads();

    float acc[4];
    const float bv = is_enc ? b1[col] : 0.f;
#pragma unroll
    for (int r = 0; r < 4; ++r) acc[r] = bv;
#pragma unroll 8
    for (int h = 0; h < Hc; ++h) {
        float w = W1[(size_t)(woff + h) * IN + col];
#pragma unroll
        for (int r = 0; r < 4; ++r) acc[r] = fmaf(x_s[r][h], w, acc[r]);
    }
#pragma unroll
    for (int r = 0; r < 4; ++r)
        Y[(size_t)(r0 + r) * IN + col] = acc[r];
}

// ---------------------------------------------------------------------------
// Kernel 2 (dominant): mma.sync bf16 joint GEMM + fused fixed-max logsumexp.
//   MT=64 rows/CTA, 103 KB dynamic smem -> 2 CTAs/SM (4 warps/SMSP).
//   A = tanh(henc+hdec) [64 x 512] bf16 (stride 520)
//   B = W2t chunks [128 n x 64 k] bf16, cp.async double-buffered, 1-ahead,
//       ONE __syncthreads per chunk.
// 256 threads = 8 warps = 2(m) x 4(n); warp tile 32 x 32; acc = 32 regs.
// ---------------------------------------------------------------------------
__global__ __launch_bounds__(256, 2) void joint_mma(
    const float* __restrict__ b2, const int* __restrict__ tokens) {
    extern __shared__ char dsm[];
    __shared__ __align__(16) float b2s[VPAD];
    __shared__ float cs[4][MT], ctk[4][MT], cbl[MT];

    const int tid = threadIdx.x;
    const int lane = tid & 31, wid = tid >> 5;
    const int warp_m = wid >> 2, warp_n = wid & 3;
    const int qr = lane >> 2, qc = lane & 3;
    const int b = blockIdx.x / BLKS_B;
    const int row0 = (blockIdx.x % BLKS_B) * MT;

    const uint32_t a_base = smemu32(dsm);
    const uint32_t b_base = a_base + A_BYTES;

    // prologue: issue B chunk 0 -> buf 0
    {
#pragma unroll
        for (int q = 0; q < 4; ++q) {
            int i = tid * 4 + q;
            int n = i >> 3, kk8 = (i & 7) * 8;
            cp_async16(b_base + (uint32_t)(n * BS + kk8) * 2,
                       g_W2t + (size_t)n * IN + kk8);
        }
        cp_commit();
    }

    for (int i = tid; i < VPAD; i += 256) b2s[i] = (i < Vc) ? b2[i] : -INFINITY;

    // ---- build A tile: h = tanh(henc[t] + hdec[u]) in bf16 ----
    {
        int t0 = row0 / U1, u0 = row0 - t0 * U1;
#pragma unroll 2
        for (int r = 0; r < MT; ++r) {
            float2 e = ((const float2*)(g_henc + (size_t)(b * Tc + t0) * IN))[tid];
            float2 d = ((const float2*)(g_hdec + (size_t)(b * U1 + u0) * IN))[tid];
            float2 hv;
            hv.x = tanh_approx(e.x + d.x);
            hv.y = tanh_approx(e.y + d.y);
            bool ok = (row0 + r) < ROWS_B;
            if (!ok) hv = make_float2(0.f, 0.f);
            *(__nv_bfloat162*)(dsm + r * (AS * 2) + tid * 4) = __float22bfloat162_rn(hv);
            if (++u0 == U1) { u0 = 0; if (t0 + 1 < Tc) ++t0; }
        }
    }

    // per-slot (4 rows/thread) state; slot s=(mi*2+half): row = warp_m*32+mi*16+half*8+qr
    float s4[4], tk4[4], bl4[4];
    int rowloc[4], tcol4[4];
#pragma unroll
    for (int s = 0; s < 4; ++s) {
        s4[s] = 0.f; tk4[s] = -INFINITY; bl4[s] = -INFINITY;
        rowloc[s] = warp_m * 32 + (s >> 1) * 16 + (s & 1) * 8 + qr;
        int row = row0 + rowloc[s];
        int u = row % U1;
        tcol4[s] = (row < ROWS_B && u < Uc) ? tokens[b * Uc + u] : -1;
    }

    // ldmatrix lane-address offsets
    const int a_row_off = (lane & 7) + ((lane >> 3) & 1) * 8;
    const int a_k_off = (lane >> 4) * 8;
    const int b_n_off = (lane & 7) + ((lane >> 4) & 1) * 8;
    const int b_k_off = ((lane >> 3) & 1) * 8;
    const uint32_t a_addr0 =
        a_base + (uint32_t)((warp_m * 32 + a_row_off) * AS + a_k_off) * 2;
    const uint32_t b_addr0 =
        b_base + (uint32_t)((warp_n * 32 + b_n_off) * BS + b_k_off) * 2;

    float acc[2][4][4];   // [mi][nf][frag] -> 32 regs

    for (int ch = 0; ch < NCHUNK; ++ch) {   // 8 ntiles x 8 kchunks of 64
        const int buf = ch & 1;
        const int nt = ch >> 3, kc = ch & 7;

        cp_wait0();           // copy(ch) complete (only group in flight)
        __syncthreads();      // visibility + all readers past chunk ch-1

        if (ch + 1 < NCHUNK) {             // issue chunk ch+1 -> other buf
            int nn = (ch + 1) >> 3, nk = (ch + 1) & 7;
            const __nv_bfloat16* src = g_W2t + (size_t)(nn * 128) * IN + nk * 64;
            uint32_t dst = b_base + ((ch + 1) & 1) * B_BYTES;
#pragma unroll
            for (int q = 0; q < 4; ++q) {
                int i = tid * 4 + q;
                int n = i >> 3, kk8 = (i & 7) * 8;
                cp_async16(dst + (uint32_t)(n * BS + kk8) * 2,
                           src + (size_t)n * IN + kk8);
            }
            cp_commit();
        }

        if (kc == 0) {
#pragma unroll
            for (int mi = 0; mi < 2; ++mi)
#pragma unroll
                for (int nf = 0; nf < 4; ++nf)
#pragma unroll
                    for (int r = 0; r < 4; ++r) acc[mi][nf][r] = 0.f;
        }

        const uint32_t bb = b_addr0 + buf * B_BYTES;
#pragma unroll
        for (int kk = 0; kk < 64; kk += 16) {
            uint32_t a[2][4], bfrg[2][4];
#pragma unroll
            for (int mi = 0; mi < 2; ++mi)
                ldmx4(a_addr0 + (uint32_t)(mi * 16 * AS + kc * 64 + kk) * 2,
                      a[mi][0], a[mi][1], a[mi][2], a[mi][3]);
#pragma unroll
            for (int ng = 0; ng < 2; ++ng)
                ldmx4(bb + (uint32_t)(ng * 16 * BS + kk) * 2,
                      bfrg[ng][0], bfrg[ng][1], bfrg[ng][2], bfrg[ng][3]);
#pragma unroll
            for (int mi = 0; mi < 2; ++mi)
#pragma unroll
                for (int nf = 0; nf < 4; ++nf) {
                    int ng = nf >> 1, pr = (nf & 1) * 2;
                    mma_bf16(acc[mi][nf][0], acc[mi][nf][1],
                             acc[mi][nf][2], acc[mi][nf][3],
                             a[mi][0], a[mi][1], a[mi][2], a[mi][3],
                             bfrg[ng][pr], bfrg[ng][pr + 1]);
                }
        }

        if (kc == 7) {
            // epilogue for n-tile nt: s += sum exp(logit); static indexing only
            const int gbase = nt * 128 + warp_n * 32;
#pragma unroll
            for (int s = 0; s < 4; ++s) {
                const int mi = s >> 1, hf = (s & 1) * 2;
                float add = 0.f;
#pragma unroll
                for (int nf = 0; nf < 4; ++nf) {
#pragma unroll
                    for (int j = 0; j < 2; ++j) {
                        int colg = gbase + nf * 8 + qc * 2 + j;
                        float lv = acc[mi][nf][hf + j] + b2s[colg];
                        add += __expf(lv);
                        if (colg == tcol4[s]) tk4[s] = lv;
                    }
                }
                s4[s] += add;
                if (nt == 0 && warp_n == 0 && qc == 0)
                    bl4[s] = acc[mi][0][hf] + b2s[0];
            }
        }
    }

    // quad reduction (lanes sharing a row)
#pragma unroll
    for (int off = 1; off <= 2; off <<= 1) {
#pragma unroll
        for (int s = 0; s < 4; ++s) {
            s4[s] += __shfl_xor_sync(0xffffffffu, s4[s], off);
            tk4[s] = fmaxf(tk4[s], __shfl_xor_sync(0xffffffffu, tk4[s], off));
            bl4[s] = fmaxf(bl4[s], __shfl_xor_sync(0xffffffffu, bl4[s], off));
        }
    }
    if (qc == 0) {
#pragma unroll
        for (int s = 0; s < 4; ++s) {
            int r = rowloc[s];
            cs[warp_n][r] = s4[s];
            ctk[warp_n][r] = tk4[s];
            if (warp_n == 0) cbl[r] = bl4[s];
        }
    }
    __syncthreads();

    if (tid < MT) {
        int row = row0 + tid;
        if (row < ROWS_B) {
            float lse = __logf(cs[0][tid] + cs[1][tid] + cs[2][tid] + cs[3][tid]);
            float tk = fmaxf(fmaxf(ctk[0][tid], ctk[1][tid]),
                             fmaxf(ctk[2][tid], ctk[3][tid]));
            int t = row / U1, u = row - t * U1;
            g_blank[(b * Tc + t) * U1 + u] = cbl[tid] - lse;
            if (u < Uc) g_label[(b * Tc + t) * Uc + u] = tk - lse;
        }
    }
}

// ---------------------------------------------------------------------------
// Kernel 3: RNN-T forward DP. One block/batch; lp staged in SMEM; wavefront
// in one warp (4 u per lane). Incremental smem offsets (+U1 / +Uc per diag)
// kill all per-diagonal address math; validity = one unsigned compare.
// ---------------------------------------------------------------------------
constexpr int DP_SMEM = (Tc * U1 + Tc * Uc) * (int)sizeof(float); // 160800

__global__ __launch_bounds__(128) void dp_kernel(
    const int* __restrict__ out_len, const int* __restrict__ tok_len) {
    extern __shared__ float lp[];
    float* blankS = lp;                 // Tc*U1
    float* labelS = lp + Tc * U1;       // Tc*Uc

    const int b = blockIdx.x, tid = threadIdx.x;
    {
        const float4* src = (const float4*)(g_blank + (size_t)b * Tc * U1);
        float4* dst = (float4*)blankS;
        for (int i = tid; i < Tc * U1 / 4; i += 128) dst[i] = src[i];
        const float4* src2 = (const float4*)(g_label + (size_t)b * Tc * Uc);
        float4* dst2 = (float4*)labelS;
        for (int i = tid; i < Tc * Uc / 4; i += 128) dst2[i] = src2[i];
    }
    const int tl = out_len[b], ul = tok_len[b];
    __syncthreads();
    if (tid >= 32) return;

    const int lane = tid;
    const int u0 = lane * 4;
    const int dstar = tl - 1 + ul;
    const int lstar = ul >> 2, jstar = ul & 3;

    float a0 = (lane == 0) ? 0.f : -INFINITY;
    float a1 = -INFINITY, a2 = -INFINITY, a3 = -INFINITY;
    float ll = 0.f;

    // Incremental offsets: at diagonal d, t = d-u.
    //   blank: (t-1)*U1 + u ; valid iff (unsigned)(t-1) < Tc-1  (t in [1,Tc-1])
    //   label: t*Uc + (u-1) ; valid iff (unsigned)t < Tc and u>=1
    int offB[4], offL[4];
    bool uok[4];   // u <= Uc (lanes 25+ partial), and u>=1 for label
    bool upos[4];
#pragma unroll
    for (int j = 0; j < 4; ++j) {
        int u = u0 + j;
        offB[j] = (1 - u - 1) * U1 + u;            // at d=1
        offL[j] = (1 - u) * Uc + (u - 1);
        uok[j]  = (u <= Uc);
        upos[j] = (u >= 1) && (u <= Uc);
    }

    // load diagonal d (guarded)
    auto loadd = [&](int d, float* cb, float* cl) {
#pragma unroll
        for (int j = 0; j < 4; ++j) {
            unsigned tm1 = (unsigned)(d - (u0 + j) - 1);   // t-1
            bool vb = uok[j] && (tm1 < (unsigned)(Tc - 1));
            bool vl = upos[j] && ((unsigned)(d - (u0 + j)) < (unsigned)Tc);
            cb[j] = vb ? blankS[offB[j]] : -INFINITY;
            cl[j] = vl ? labelS[offL[j]] : -INFINITY;
            offB[j] += U1;
            offL[j] += Uc;
        }
    };

    float cb[4], cl[4];
    loadd(1, cb, cl);

    for (int d = 1; d <= (Tc - 1) + Uc; ++d) {
        float nb[4], nl[4];
        loadd(d + 1, nb, nl);                        // prefetch next diag
        float up = __shfl_up_sync(0xffffffffu, a3, 1);
        float x0 = a0 + cb[0], y0 = up + cl[0];
        float x1 = a1 + cb[1], y1 = a0 + cl[1];
        float x2 = a2 + cb[2], y2 = a1 + cl[2];
        float x3 = a3 + cb[3], y3 = a2 + cl[3];
        {
            float h = fmaxf(x0, y0), l = fminf(x0, y0);
            a0 = (l == -INFINITY) ? h : h + __logf(1.f + __expf(l - h));
        }
        {
            float h = fmaxf(x1, y1), l = fminf(x1, y1);
            a1 = (l == -INFINITY) ? h : h + __logf(1.f + __expf(l - h));
        }
        {
            float h = fmaxf(x2, y2), l = fminf(x2, y2);
            a2 = (l == -INFINITY) ? h : h + __logf(1.f + __expf(l - h));
        }
        {
            float h = fmaxf(x3, y3), l = fminf(x3, y3);
            a3 = (l == -INFINITY) ? h : h + __logf(1.f + __expf(l - h));
        }
        if (d == dstar && lane == lstar) {
            ll = (jstar == 0) ? a0 : (jstar == 1) ? a1
               : (jstar == 2) ? a2 : a3;
        }
#pragma unroll
        for (int j = 0; j < 4; ++j) { cb[j] = nb[j]; cl[j] = nl[j]; }
    }
    if (lane == lstar)
        g_ll[b] = ll + blankS[(tl - 1) * U1 + ul];
}

__global__ void finalize_kernel(float* out) {
    out[0] = -0.25f * (g_ll[0] + g_ll[1] + g_ll[2] + g_ll[3]);
}

// ---------------------------------------------------------------------------
extern "C" void kernel_launch(void* const* d_in, const int* in_sizes, int n_in,
                              void* d_out, int out_size) {
    const float* enc     = (const float*)d_in[0];
    const float* dec     = (const float*)d_in[1];
    const int*   tokens  = (const int*)d_in[2];
    const int*   out_len = (const int*)d_in[3];
    const int*   tok_len = (const int*)d_in[4];
    const float* W1      = (const float*)d_in[5];
    const float* b1      = (const float*)d_in[6];
    const float* W2      = (const float*)d_in[7];
    const float* b2      = (const float*)d_in[8];
    float* out = (float*)d_out;

    cudaFuncSetAttribute(joint_mma, cudaFuncAttributeMaxDynamicSharedMemorySize, DSMEM);
    cudaFuncSetAttribute(dp_kernel, cudaFuncAttributeMaxDynamicSharedMemorySize, DP_SMEM);

    w2prep<<<dim3(IN / 32, VPAD / 32), 256>>>(W2);
    proj_kernel<<<dim3(ENC_BLKS + DEC_BLKS, 4), 128>>>(enc, dec, W1, b1);
    joint_mma<<<Bc * BLKS_B, 256, DSMEM>>>(b2, tokens);
    dp_kernel<<<Bc, 128, DP_SMEM>>>(out_len, tok_len);
    finalize_kernel<<<1, 1>>>(out);
}

// round 7
// speedup vs baseline: 2.2370x; 1.4832x over previous
#include <cuda_runtime.h>
#include <cuda_bf16.h>
#include <math.h>
#include <stdint.h>

#define DEV_INLINE __device__ __forceinline__

// Problem constants
constexpr int Bc = 4, Tc = 200, Uc = 100, U1 = 101, Hc = 320, IN = 512, Vc = 1000;
constexpr int ROWS_B = Tc * U1;                    // 20200 rows (t,u) per batch
constexpr int MT = 64;                             // rows per CTA
constexpr int VPAD = 1024;                         // V padded to 8x128
constexpr int BLKS_B = (ROWS_B + MT - 1) / MT;     // 316

constexpr int ASB = 528;                           // A row stride BYTES (512 + 16)
constexpr int BSB = 144;                           // B row stride BYTES (128 + 16)
constexpr int A_BYTES = MT * ASB;                  // 33792
constexpr int B_BYTES = 128 * BSB;                 // 18432
constexpr int DSMEM = A_BYTES + 2 * B_BYTES;       // 70656
constexpr int NCHUNK = 32;                         // 8 ntiles x 4 kchunks(128 fp8)
constexpr float SCALE_INV = 1.0f / 256.0f;         // (16*h)*(16*w) -> /256

// Scratch (no allocations allowed -> device globals)
__device__ __align__(16) float g_henc[Bc * Tc * IN];
__device__ __align__(16) float g_hdec[Bc * U1 * IN];
__device__ __align__(16) uint8_t g_W2q[VPAD * IN];   // fp8(16*W2^T) [v][k]
__device__ __align__(16) float g_blank[Bc * Tc * U1];
__device__ __align__(16) float g_label[Bc * Tc * Uc];
__device__ float g_ll[Bc];

// ---------------------------------------------------------------------------
// Helpers
// ---------------------------------------------------------------------------
DEV_INLINE float tanh_approx(float x) {
    float y; asm("tanh.approx.f32 %0, %1;" : "=f"(y) : "f"(x)); return y;
}
DEV_INLINE uint32_t smemu32(const void* p) {
    uint32_t a;
    asm("{ .reg .u64 t; cvta.to.shared.u64 t, %1; cvt.u32.u64 %0, t; }" : "=r"(a) : "l"(p));
    return a;
}
DEV_INLINE void cp_async16(uint32_t dst, const void* src) {
    asm volatile("cp.async.ca.shared.global [%0], [%1], 16;"
                 :: "r"(dst), "l"(src) : "memory");
}
DEV_INLINE void cp_commit() { asm volatile("cp.async.commit_group;" ::: "memory"); }
DEV_INLINE void cp_wait0()  { asm volatile("cp.async.wait_group 0;" ::: "memory"); }

DEV_INLINE void ldmx4(uint32_t addr, uint32_t& r0, uint32_t& r1, uint32_t& r2, uint32_t& r3) {
    asm volatile("ldmatrix.sync.aligned.m8n8.x4.shared.b16 {%0,%1,%2,%3}, [%4];"
                 : "=r"(r0), "=r"(r1), "=r"(r2), "=r"(r3) : "r"(addr));
}
// fp8 e4m3 MMA: m16n8k32, byte-layout-compatible with bf16 m16n8k16 fragments
DEV_INLINE void mma_fp8(float& c0, float& c1, float& c2, float& c3,
                        uint32_t a0, uint32_t a1, uint32_t a2, uint32_t a3,
                        uint32_t b0, uint32_t b1) {
    asm volatile(
        "mma.sync.aligned.m16n8k32.row.col.f32.e4m3.e4m3.f32 "
        "{%0,%1,%2,%3}, {%4,%5,%6,%7}, {%8,%9}, {%0,%1,%2,%3};"
        : "+f"(c0), "+f"(c1), "+f"(c2), "+f"(c3)
        : "r"(a0), "r"(a1), "r"(a2), "r"(a3), "r"(b0), "r"(b1));
}
// pack 4 consecutive floats (k, k+1, k+2, k+3) into 4 e4m3 bytes
DEV_INLINE uint32_t pack_e4m3x4(float f0, float f1, float f2, float f3) {
    uint16_t lo, hi;
    asm("cvt.rn.satfinite.e4m3x2.f32 %0, %1, %2;" : "=h"(lo) : "f"(f1), "f"(f0));
    asm("cvt.rn.satfinite.e4m3x2.f32 %0, %1, %2;" : "=h"(hi) : "f"(f3), "f"(f2));
    return (uint32_t)lo | ((uint32_t)hi << 16);
}

// ---------------------------------------------------------------------------
// Kernel 0: W2 [512][1000] fp32 -> g_W2q [1024][512] fp8(16*w), transpose+pad
// ---------------------------------------------------------------------------
__global__ __launch_bounds__(256) void w2prep(const float* __restrict__ W2) {
    __shared__ float tile[32][33];
    const int kb = blockIdx.x * 32, vb = blockIdx.y * 32;
    const int tx = threadIdx.x & 31, ty = threadIdx.x >> 5;
#pragma unroll
    for (int i = 0; i < 4; ++i) {
        int k = kb + ty + 8 * i, v = vb + tx;
        tile[ty + 8 * i][tx] = (v < Vc) ? W2[(size_t)k * Vc + v] : 0.f;
    }
    __syncthreads();
    // thread -> (v_loc = tid>>3, k_loc = (tid&7)*4); pack 4 k's into one u32
    const int v_loc = threadIdx.x >> 3;
    const int k_loc = (threadIdx.x & 7) * 4;
    uint32_t pk = pack_e4m3x4(16.f * tile[k_loc + 0][v_loc],
                              16.f * tile[k_loc + 1][v_loc],
                              16.f * tile[k_loc + 2][v_loc],
                              16.f * tile[k_loc + 3][v_loc]);
    *(uint32_t*)(g_W2q + (size_t)(vb + v_loc) * IN + kb + k_loc) = pk;
}

// ---------------------------------------------------------------------------
// Kernel 1: projections  h_enc = enc @ W1[:H] + b1 ; h_dec = dec @ W1[H:]
// 4 rows x 128 cols per block; grid (301, 4) = 1204 blocks.
// ---------------------------------------------------------------------------
constexpr int ENC_BLKS = (Bc * Tc) / 4;            // 200
constexpr int DEC_BLKS = (Bc * U1) / 4;            // 101

__global__ __launch_bounds__(128) void proj_kernel(
    const float* __restrict__ enc, const float* __restrict__ dec,
    const float* __restrict__ W1, const float* __restrict__ b1) {
    __shared__ float x_s[4][Hc];
    const int blk = blockIdx.x;
    const bool is_enc = blk < ENC_BLKS;
    const int r0 = (is_enc ? blk : blk - ENC_BLKS) * 4;
    const float* __restrict__ X = is_enc ? enc : dec;
    float* __restrict__ Y = is_enc ? g_henc : g_hdec;
    const int woff = is_enc ? 0 : Hc;
    const int col = blockIdx.y * 128 + threadIdx.x;

    for (int idx = threadIdx.x; idx < 4 * Hc; idx += 128) {
        int r = idx / Hc, i = idx - r * Hc;
        x_s[r][i] = X[(size_t)(r0 + r) * Hc + i];
    }
    __syncthreads();

    float acc[4];
    const float bv = is_enc ? b1[col] : 0.f;
#pragma unroll
    for (int r = 0; r < 4; ++r) acc[r] = bv;
#pragma unroll 8
    for (int h = 0; h < Hc; ++h) {
        float w = W1[(size_t)(woff + h) * IN + col];
#pragma unroll
        for (int r = 0; r < 4; ++r) acc[r] = fmaf(x_s[r][h], w, acc[r]);
    }
#pragma unroll
    for (int r = 0; r < 4; ++r)
        Y[(size_t)(r0 + r) * IN + col] = acc[r];
}

// ---------------------------------------------------------------------------
// Kernel 2 (dominant): fp8 mma.sync joint GEMM + fused fixed-max logsumexp.
//   A = fp8(16*tanh(henc+hdec)) [64 x 512] (row stride 528 B, conflict-free)
//   B = fp8(16*W2t) chunks [128 n x 128 k], cp.async double-buffered, 1-ahead
//   acc = 256 * logits (fp32); epilogue: lv = acc/256 + b2.
// 256 threads = 8 warps = 2(m) x 4(n); warp tile 32 x 32.
// ---------------------------------------------------------------------------
__global__ __launch_bounds__(256, 2) void joint_mma(
    const float* __restrict__ b2, const int* __restrict__ tokens) {
    extern __shared__ char dsm[];
    __shared__ __align__(16) float b2s[VPAD];
    __shared__ float cs[4][MT], ctk[4][MT], cbl[MT];

    const int tid = threadIdx.x;
    const int lane = tid & 31, wid = tid >> 5;
    const int warp_m = wid >> 2, warp_n = wid & 3;
    const int qr = lane >> 2, qc = lane & 3;
    const int b = blockIdx.x / BLKS_B;
    const int row0 = (blockIdx.x % BLKS_B) * MT;

    const uint32_t a_base = smemu32(dsm);
    const uint32_t b_base = a_base + A_BYTES;

    // cp.async mapping: i = tid*4+q -> row n = i>>3 (128B/row), koff = (i&7)*16
    // prologue: issue B chunk 0 -> buf 0
    {
#pragma unroll
        for (int q = 0; q < 4; ++q) {
            int i = tid * 4 + q;
            int n = i >> 3, koff = (i & 7) * 16;
            cp_async16(b_base + (uint32_t)(n * BSB + koff),
                       g_W2q + (size_t)n * IN + koff);
        }
        cp_commit();
    }

    for (int i = tid; i < VPAD; i += 256) b2s[i] = (i < Vc) ? b2[i] : -INFINITY;

    // ---- build A tile: fp8(16 * tanh(henc[t] + hdec[u])) ----
    {
        const int rh = tid >> 7;              // 0/1: which of the 2 rows
        const int kt = (tid & 127) * 4;       // k offset
#pragma unroll 2
        for (int r2 = 0; r2 < MT; r2 += 2) {
            int r = r2 + rh;
            int row = row0 + r;
            uint32_t pk = 0;
            if (row < ROWS_B) {
                int t = row / U1, u = row - t * U1;
                float4 e = *(const float4*)(g_henc + (size_t)(b * Tc + t) * IN + kt);
                float4 d = *(const float4*)(g_hdec + (size_t)(b * U1 + u) * IN + kt);
                pk = pack_e4m3x4(16.f * tanh_approx(e.x + d.x),
                                 16.f * tanh_approx(e.y + d.y),
                                 16.f * tanh_approx(e.z + d.z),
                                 16.f * tanh_approx(e.w + d.w));
            }
            *(uint32_t*)(dsm + r * ASB + kt) = pk;
        }
    }

    // per-slot (4 rows/thread) state
    float s4[4], tk4[4], bl4[4];
    int rowloc[4], tcol4[4];
#pragma unroll
    for (int s = 0; s < 4; ++s) {
        s4[s] = 0.f; tk4[s] = -INFINITY; bl4[s] = -INFINITY;
        rowloc[s] = warp_m * 32 + (s >> 1) * 16 + (s & 1) * 8 + qr;
        int row = row0 + rowloc[s];
        int u = row % U1;
        tcol4[s] = (row < ROWS_B && u < Uc) ? tokens[b * Uc + u] : -1;
    }

    // ldmatrix lane addressing (b16 view of fp8 bytes)
    const int a_row_off = (lane & 7) + ((lane >> 3) & 1) * 8;
    const int a_kb_off = (lane >> 4) * 16;              // bytes
    const int b_n_off = (lane & 7) + ((lane >> 4) & 1) * 8;
    const int b_kb_off = ((lane >> 3) & 1) * 16;        // bytes
    const uint32_t a_addr0 =
        a_base + (uint32_t)((warp_m * 32 + a_row_off) * ASB + a_kb_off);
    const uint32_t b_addr0 =
        b_base + (uint32_t)((warp_n * 32 + b_n_off) * BSB + b_kb_off);

    float acc[2][4][4];   // [mi][nf][frag] -> 32 regs

    for (int ch = 0; ch < NCHUNK; ++ch) {   // 8 ntiles x 4 kchunks of 128 fp8
        const int buf = ch & 1;
        const int nt = ch >> 2, kc = ch & 3;

        cp_wait0();
        __syncthreads();

        if (ch + 1 < NCHUNK) {             // issue chunk ch+1 -> other buf
            int nn = (ch + 1) >> 2, nk = (ch + 1) & 3;
            const uint8_t* src = g_W2q + (size_t)(nn * 128) * IN + nk * 128;
            uint32_t dst = b_base + ((ch + 1) & 1) * B_BYTES;
#pragma unroll
            for (int q = 0; q < 4; ++q) {
                int i = tid * 4 + q;
                int n = i >> 3, koff = (i & 7) * 16;
                cp_async16(dst + (uint32_t)(n * BSB + koff),
                           src + (size_t)n * IN + koff);
            }
            cp_commit();
        }

        if (kc == 0) {
#pragma unroll
            for (int mi = 0; mi < 2; ++mi)
#pragma unroll
                for (int nf = 0; nf < 4; ++nf)
#pragma unroll
                    for (int r = 0; r < 4; ++r) acc[mi][nf][r] = 0.f;
        }

        const uint32_t bb = b_addr0 + buf * B_BYTES;
#pragma unroll
        for (int kk = 0; kk < 4; ++kk) {   // 4 x k32 fp8 (32 B each)
            uint32_t a[2][4], bfrg[2][4];
#pragma unroll
            for (int mi = 0; mi < 2; ++mi)
                ldmx4(a_addr0 + (uint32_t)(mi * 16 * ASB + kc * 128 + kk * 32),
                      a[mi][0], a[mi][1], a[mi][2], a[mi][3]);
#pragma unroll
            for (int ng = 0; ng < 2; ++ng)
                ldmx4(bb + (uint32_t)(ng * 16 * BSB + kk * 32),
                      bfrg[ng][0], bfrg[ng][1], bfrg[ng][2], bfrg[ng][3]);
#pragma unroll
            for (int mi = 0; mi < 2; ++mi)
#pragma unroll
                for (int nf = 0; nf < 4; ++nf) {
                    int ng = nf >> 1, pr = (nf & 1) * 2;
                    mma_fp8(acc[mi][nf][0], acc[mi][nf][1],
                            acc[mi][nf][2], acc[mi][nf][3],
                            a[mi][0], a[mi][1], a[mi][2], a[mi][3],
                            bfrg[ng][pr], bfrg[ng][pr + 1]);
                }
        }

        if (kc == 3) {
            // epilogue for n-tile nt: s += sum exp(acc/256 + b2)
            const int gbase = nt * 128 + warp_n * 32;
#pragma unroll
            for (int s = 0; s < 4; ++s) {
                const int mi = s >> 1, hf = (s & 1) * 2;
                float add = 0.f;
#pragma unroll
                for (int nf = 0; nf < 4; ++nf) {
#pragma unroll
                    for (int j = 0; j < 2; ++j) {
                        int colg = gbase + nf * 8 + qc * 2 + j;
                        float lv = fmaf(acc[mi][nf][hf + j], SCALE_INV, b2s[colg]);
                        add += __expf(lv);
                        if (colg == tcol4[s]) tk4[s] = lv;
                    }
                }
                s4[s] += add;
                if (nt == 0 && warp_n == 0 && qc == 0)
                    bl4[s] = fmaf(acc[mi][0][hf], SCALE_INV, b2s[0]);
            }
        }
    }

    // quad reduction (lanes sharing a row)
#pragma unroll
    for (int off = 1; off <= 2; off <<= 1) {
#pragma unroll
        for (int s = 0; s < 4; ++s) {
            s4[s] += __shfl_xor_sync(0xffffffffu, s4[s], off);
            tk4[s] = fmaxf(tk4[s], __shfl_xor_sync(0xffffffffu, tk4[s], off));
            bl4[s] = fmaxf(bl4[s], __shfl_xor_sync(0xffffffffu, bl4[s], off));
        }
    }
    if (qc == 0) {
#pragma unroll
        for (int s = 0; s < 4; ++s) {
            int r = rowloc[s];
            cs[warp_n][r] = s4[s];
            ctk[warp_n][r] = tk4[s];
            if (warp_n == 0) cbl[r] = bl4[s];
        }
    }
    __syncthreads();

    if (tid < MT) {
        int row = row0 + tid;
        if (row < ROWS_B) {
            float lse = __logf(cs[0][tid] + cs[1][tid] + cs[2][tid] + cs[3][tid]);
            float tk = fmaxf(fmaxf(ctk[0][tid], ctk[1][tid]),
                             fmaxf(ctk[2][tid], ctk[3][tid]));
            int t = row / U1, u = row - t * U1;
            g_blank[(b * Tc + t) * U1 + u] = cbl[tid] - lse;
            if (u < Uc) g_label[(b * Tc + t) * Uc + u] = tk - lse;
        }
    }
}

// ---------------------------------------------------------------------------
// Kernel 3: RNN-T forward DP (round-3 version: best measured at 94 us).
// One block per batch, lp staged in SMEM, block-wide anti-diagonal wavefront.
// ---------------------------------------------------------------------------
constexpr int DP_SMEM = (Tc * U1 + Tc * Uc) * (int)sizeof(float); // 160800

__global__ __launch_bounds__(128) void dp_kernel(
    const int* __restrict__ out_len, const int* __restrict__ tok_len) {
    extern __shared__ float lp[];
    float* blankS = lp;
    float* labelS = lp + Tc * U1;
    __shared__ float bufA[U1 + 1], bufB[U1 + 1];
    __shared__ float llk;

    const int b = blockIdx.x, tid = threadIdx.x;
    {
        const float4* src = (const float4*)(g_blank + (size_t)b * Tc * U1);
        float4* dst = (float4*)blankS;
        for (int i = tid; i < Tc * U1 / 4; i += 128) dst[i] = src[i];
        const float4* src2 = (const float4*)(g_label + (size_t)b * Tc * Uc);
        float4* dst2 = (float4*)labelS;
        for (int i = tid; i < Tc * Uc / 4; i += 128) dst2[i] = src2[i];
    }
    const int tl = out_len[b], ul = tok_len[b];
    __syncthreads();

    float* prev = bufA;
    float* cur = bufB;
    const int u = tid;
    const bool ok = (u <= Uc);

    for (int d = 0; d <= (Tc - 1) + Uc; ++d) {
        int t = d - u;
        if (ok && t >= 0 && t < Tc) {
            float val;
            if (d == 0) {
                val = 0.f;
            } else {
                float x = (t >= 1) ? prev[u] + blankS[(t - 1) * U1 + u] : -INFINITY;
                float y = (u >= 1) ? prev[u - 1] + labelS[t * Uc + (u - 1)] : -INFINITY;
                float hi = fmaxf(x, y), lo = fminf(x, y);
                val = (lo == -INFINITY) ? hi : hi + log1pf(__expf(lo - hi));
            }
            cur[u] = val;
            if (t == tl - 1 && u == ul) llk = val;
        }
        __syncthreads();
        float* tmp = prev; prev = cur; cur = tmp;
    }
    if (tid == 0) g_ll[b] = llk + blankS[(tl - 1) * U1 + ul];
}

__global__ void finalize_kernel(float* out) {
    out[0] = -0.25f * (g_ll[0] + g_ll[1] + g_ll[2] + g_ll[3]);
}

// ---------------------------------------------------------------------------
extern "C" void kernel_launch(void* const* d_in, const int* in_sizes, int n_in,
                              void* d_out, int out_size) {
    const float* enc     = (const float*)d_in[0];
    const float* dec     = (const float*)d_in[1];
    const int*   tokens  = (const int*)d_in[2];
    const int*   out_len = (const int*)d_in[3];
    const int*   tok_len = (const int*)d_in[4];
    const float* W1      = (const float*)d_in[5];
    const float* b1      = (const float*)d_in[6];
    const float* W2      = (const float*)d_in[7];
    const float* b2      = (const float*)d_in[8];
    float* out = (float*)d_out;

    cudaFuncSetAttribute(joint_mma, cudaFuncAttributeMaxDynamicSharedMemorySize, DSMEM);
    cudaFuncSetAttribute(dp_kernel, cudaFuncAttributeMaxDynamicSharedMemorySize, DP_SMEM);

    w2prep<<<dim3(IN / 32, VPAD / 32), 256>>>(W2);
    proj_kernel<<<dim3(ENC_BLKS + DEC_BLKS, 4), 128>>>(enc, dec, W1, b1);
    joint_mma<<<Bc * BLKS_B, 256, DSMEM>>>(b2, tokens);
    dp_kernel<<<Bc, 128, DP_SMEM>>>(out_len, tok_len);
    finalize_kernel<<<1, 1>>>(out);
}

// round 8
// speedup vs baseline: 2.3119x; 1.0335x over previous
#include <cuda_runtime.h>
#include <cuda_bf16.h>
#include <math.h>
#include <stdint.h>

#define DEV_INLINE __device__ __forceinline__

// Problem constants
constexpr int Bc = 4, Tc = 200, Uc = 100, U1 = 101, Hc = 320, IN = 512, Vc = 1000;
constexpr int ROWS_B = Tc * U1;                    // 20200 rows (t,u) per batch
constexpr int MT = 64;                             // rows per CTA
constexpr int VPAD = 1024;                         // V padded to 8x128
constexpr int BLKS_B = (ROWS_B + MT - 1) / MT;     // 316

constexpr int ASB = 528;                           // A row stride BYTES (512 + 16)
constexpr int BSB = 144;                           // B row stride BYTES (128 + 16)
constexpr int A_BYTES = MT * ASB;                  // 33792
constexpr int B_BYTES = 128 * BSB;                 // 18432
constexpr int DSMEM = A_BYTES + 2 * B_BYTES;       // 70656
constexpr int NCHUNK = 32;                         // 8 ntiles x 4 kchunks(128 fp8)
constexpr float SCALE_INV = 1.0f / 256.0f;         // (16*h)*(16*w) -> /256

// Scratch (no allocations allowed -> device globals)
__device__ __align__(16) float g_henc[Bc * Tc * IN];
__device__ __align__(16) float g_hdec[Bc * U1 * IN];
__device__ __align__(16) uint8_t g_W2q[VPAD * IN];   // fp8(16*W2^T) [v][k]
__device__ __align__(16) float g_blank[Bc * Tc * U1];
__device__ __align__(16) float g_label[Bc * Tc * Uc];
__device__ float g_ll[Bc];
__device__ int g_done;                               // zero-init; winner resets

// ---------------------------------------------------------------------------
// Helpers
// ---------------------------------------------------------------------------
DEV_INLINE float tanh_approx(float x) {
    float y; asm("tanh.approx.f32 %0, %1;" : "=f"(y) : "f"(x)); return y;
}
DEV_INLINE uint32_t smemu32(const void* p) {
    uint32_t a;
    asm("{ .reg .u64 t; cvta.to.shared.u64 t, %1; cvt.u32.u64 %0, t; }" : "=r"(a) : "l"(p));
    return a;
}
DEV_INLINE void cp_async16(uint32_t dst, const void* src) {
    asm volatile("cp.async.ca.shared.global [%0], [%1], 16;"
                 :: "r"(dst), "l"(src) : "memory");
}
DEV_INLINE void cp_commit() { asm volatile("cp.async.commit_group;" ::: "memory"); }
DEV_INLINE void cp_wait0()  { asm volatile("cp.async.wait_group 0;" ::: "memory"); }

DEV_INLINE void ldmx4(uint32_t addr, uint32_t& r0, uint32_t& r1, uint32_t& r2, uint32_t& r3) {
    asm volatile("ldmatrix.sync.aligned.m8n8.x4.shared.b16 {%0,%1,%2,%3}, [%4];"
                 : "=r"(r0), "=r"(r1), "=r"(r2), "=r"(r3) : "r"(addr));
}
DEV_INLINE void mma_fp8(float& c0, float& c1, float& c2, float& c3,
                        uint32_t a0, uint32_t a1, uint32_t a2, uint32_t a3,
                        uint32_t b0, uint32_t b1) {
    asm volatile(
        "mma.sync.aligned.m16n8k32.row.col.f32.e4m3.e4m3.f32 "
        "{%0,%1,%2,%3}, {%4,%5,%6,%7}, {%8,%9}, {%0,%1,%2,%3};"
        : "+f"(c0), "+f"(c1), "+f"(c2), "+f"(c3)
        : "r"(a0), "r"(a1), "r"(a2), "r"(a3), "r"(b0), "r"(b1));
}
DEV_INLINE uint32_t pack_e4m3x4(float f0, float f1, float f2, float f3) {
    uint16_t lo, hi;
    asm("cvt.rn.satfinite.e4m3x2.f32 %0, %1, %2;" : "=h"(lo) : "f"(f1), "f"(f0));
    asm("cvt.rn.satfinite.e4m3x2.f32 %0, %1, %2;" : "=h"(hi) : "f"(f3), "f"(f2));
    return (uint32_t)lo | ((uint32_t)hi << 16);
}

// ---------------------------------------------------------------------------
// Kernel 0 (merged prep): W2 transpose/quantize + both projections.
//   blocks [0, W2_BLKS)            : W2 [512][1000] f32 -> fp8(16*w) [1024][512]
//   blocks [W2_BLKS, +PENC_BLKS)   : h_enc = enc @ W1[:H] + b1   (4 rows x 256 cols)
//   blocks [.., +PDEC_BLKS)        : h_dec = dec @ W1[H:]
// ---------------------------------------------------------------------------
constexpr int W2_BLKS = (IN / 32) * (VPAD / 32);   // 512
constexpr int PENC_BLKS = (Bc * Tc / 4) * 2;       // 400
constexpr int PDEC_BLKS = (Bc * U1 / 4) * 2;       // 202
constexpr int PREP_BLKS = W2_BLKS + PENC_BLKS + PDEC_BLKS;  // 1114

__global__ __launch_bounds__(256) void prep_kernel(
    const float* __restrict__ W2,
    const float* __restrict__ enc, const float* __restrict__ dec,
    const float* __restrict__ W1, const float* __restrict__ b1) {
    const int blk = blockIdx.x;
    const int tid = threadIdx.x;

    if (blk < W2_BLKS) {
        __shared__ float tile[32][33];
        const int kb = (blk & 15) * 32, vb = (blk >> 4) * 32;
        const int tx = tid & 31, ty = tid >> 5;
#pragma unroll
        for (int i = 0; i < 4; ++i) {
            int k = kb + ty + 8 * i, v = vb + tx;
            tile[ty + 8 * i][tx] = (v < Vc) ? W2[(size_t)k * Vc + v] : 0.f;
        }
        __syncthreads();
        const int v_loc = tid >> 3;
        const int k_loc = (tid & 7) * 4;
        uint32_t pk = pack_e4m3x4(16.f * tile[k_loc + 0][v_loc],
                                  16.f * tile[k_loc + 1][v_loc],
                                  16.f * tile[k_loc + 2][v_loc],
                                  16.f * tile[k_loc + 3][v_loc]);
        *(uint32_t*)(g_W2q + (size_t)(vb + v_loc) * IN + kb + k_loc) = pk;
        return;
    }

    // ---- projection part ----
    __shared__ float x_s[4][Hc];
    const int pb = blk - W2_BLKS;
    const bool is_enc = pb < PENC_BLKS;
    const int lb = is_enc ? pb : pb - PENC_BLKS;
    const int r0 = (lb >> 1) * 4;
    const int col = (lb & 1) * 256 + tid;
    const float* __restrict__ X = is_enc ? enc : dec;
    float* __restrict__ Y = is_enc ? g_henc : g_hdec;
    const int woff = is_enc ? 0 : Hc;

    for (int idx = tid; idx < 4 * Hc; idx += 256) {
        int r = idx / Hc, i = idx - r * Hc;
        x_s[r][i] = X[(size_t)(r0 + r) * Hc + i];
    }
    __syncthreads();

    float acc[4];
    const float bv = is_enc ? b1[col] : 0.f;
#pragma unroll
    for (int r = 0; r < 4; ++r) acc[r] = bv;
#pragma unroll 8
    for (int h = 0; h < Hc; ++h) {
        float w = W1[(size_t)(woff + h) * IN + col];
#pragma unroll
        for (int r = 0; r < 4; ++r) acc[r] = fmaf(x_s[r][h], w, acc[r]);
    }
#pragma unroll
    for (int r = 0; r < 4; ++r)
        Y[(size_t)(r0 + r) * IN + col] = acc[r];
}

// ---------------------------------------------------------------------------
// Kernel 1 (dominant): fp8 mma.sync joint GEMM + fused fixed-max logsumexp.
// (unchanged from round 7 — measured ~210 us)
// ---------------------------------------------------------------------------
__global__ __launch_bounds__(256, 2) void joint_mma(
    const float* __restrict__ b2, const int* __restrict__ tokens) {
    extern __shared__ char dsm[];
    __shared__ __align__(16) float b2s[VPAD];
    __shared__ float cs[4][MT], ctk[4][MT], cbl[MT];

    const int tid = threadIdx.x;
    const int lane = tid & 31, wid = tid >> 5;
    const int warp_m = wid >> 2, warp_n = wid & 3;
    const int qr = lane >> 2, qc = lane & 3;
    const int b = blockIdx.x / BLKS_B;
    const int row0 = (blockIdx.x % BLKS_B) * MT;

    const uint32_t a_base = smemu32(dsm);
    const uint32_t b_base = a_base + A_BYTES;

    // prologue: issue B chunk 0 -> buf 0
    {
#pragma unroll
        for (int q = 0; q < 4; ++q) {
            int i = tid * 4 + q;
            int n = i >> 3, koff = (i & 7) * 16;
            cp_async16(b_base + (uint32_t)(n * BSB + koff),
                       g_W2q + (size_t)n * IN + koff);
        }
        cp_commit();
    }

    for (int i = tid; i < VPAD; i += 256) b2s[i] = (i < Vc) ? b2[i] : -INFINITY;

    // ---- build A tile: fp8(16 * tanh(henc[t] + hdec[u])) ----
    {
        const int rh = tid >> 7;
        const int kt = (tid & 127) * 4;
#pragma unroll 2
        for (int r2 = 0; r2 < MT; r2 += 2) {
            int r = r2 + rh;
            int row = row0 + r;
            uint32_t pk = 0;
            if (row < ROWS_B) {
                int t = row / U1, u = row - t * U1;
                float4 e = *(const float4*)(g_henc + (size_t)(b * Tc + t) * IN + kt);
                float4 d = *(const float4*)(g_hdec + (size_t)(b * U1 + u) * IN + kt);
                pk = pack_e4m3x4(16.f * tanh_approx(e.x + d.x),
                                 16.f * tanh_approx(e.y + d.y),
                                 16.f * tanh_approx(e.z + d.z),
                                 16.f * tanh_approx(e.w + d.w));
            }
            *(uint32_t*)(dsm + r * ASB + kt) = pk;
        }
    }

    float s4[4], tk4[4], bl4[4];
    int rowloc[4], tcol4[4];
#pragma unroll
    for (int s = 0; s < 4; ++s) {
        s4[s] = 0.f; tk4[s] = -INFINITY; bl4[s] = -INFINITY;
        rowloc[s] = warp_m * 32 + (s >> 1) * 16 + (s & 1) * 8 + qr;
        int row = row0 + rowloc[s];
        int u = row % U1;
        tcol4[s] = (row < ROWS_B && u < Uc) ? tokens[b * Uc + u] : -1;
    }

    const int a_row_off = (lane & 7) + ((lane >> 3) & 1) * 8;
    const int a_kb_off = (lane >> 4) * 16;
    const int b_n_off = (lane & 7) + ((lane >> 4) & 1) * 8;
    const int b_kb_off = ((lane >> 3) & 1) * 16;
    const uint32_t a_addr0 =
        a_base + (uint32_t)((warp_m * 32 + a_row_off) * ASB + a_kb_off);
    const uint32_t b_addr0 =
        b_base + (uint32_t)((warp_n * 32 + b_n_off) * BSB + b_kb_off);

    float acc[2][4][4];

    for (int ch = 0; ch < NCHUNK; ++ch) {
        const int buf = ch & 1;
        const int nt = ch >> 2, kc = ch & 3;

        cp_wait0();
        __syncthreads();

        if (ch + 1 < NCHUNK) {
            int nn = (ch + 1) >> 2, nk = (ch + 1) & 3;
            const uint8_t* src = g_W2q + (size_t)(nn * 128) * IN + nk * 128;
            uint32_t dst = b_base + ((ch + 1) & 1) * B_BYTES;
#pragma unroll
            for (int q = 0; q < 4; ++q) {
                int i = tid * 4 + q;
                int n = i >> 3, koff = (i & 7) * 16;
                cp_async16(dst + (uint32_t)(n * BSB + koff),
                           src + (size_t)n * IN + koff);
            }
            cp_commit();
        }

        if (kc == 0) {
#pragma unroll
            for (int mi = 0; mi < 2; ++mi)
#pragma unroll
                for (int nf = 0; nf < 4; ++nf)
#pragma unroll
                    for (int r = 0; r < 4; ++r) acc[mi][nf][r] = 0.f;
        }

        const uint32_t bb = b_addr0 + buf * B_BYTES;
#pragma unroll
        for (int kk = 0; kk < 4; ++kk) {
            uint32_t a[2][4], bfrg[2][4];
#pragma unroll
            for (int mi = 0; mi < 2; ++mi)
                ldmx4(a_addr0 + (uint32_t)(mi * 16 * ASB + kc * 128 + kk * 32),
                      a[mi][0], a[mi][1], a[mi][2], a[mi][3]);
#pragma unroll
            for (int ng = 0; ng < 2; ++ng)
                ldmx4(bb + (uint32_t)(ng * 16 * BSB + kk * 32),
                      bfrg[ng][0], bfrg[ng][1], bfrg[ng][2], bfrg[ng][3]);
#pragma unroll
            for (int mi = 0; mi < 2; ++mi)
#pragma unroll
                for (int nf = 0; nf < 4; ++nf) {
                    int ng = nf >> 1, pr = (nf & 1) * 2;
                    mma_fp8(acc[mi][nf][0], acc[mi][nf][1],
                            acc[mi][nf][2], acc[mi][nf][3],
                            a[mi][0], a[mi][1], a[mi][2], a[mi][3],
                            bfrg[ng][pr], bfrg[ng][pr + 1]);
                }
        }

        if (kc == 3) {
            const int gbase = nt * 128 + warp_n * 32;
#pragma unroll
            for (int s = 0; s < 4; ++s) {
                const int mi = s >> 1, hf = (s & 1) * 2;
                float add = 0.f;
#pragma unroll
                for (int nf = 0; nf < 4; ++nf) {
#pragma unroll
                    for (int j = 0; j < 2; ++j) {
                        int colg = gbase + nf * 8 + qc * 2 + j;
                        float lv = fmaf(acc[mi][nf][hf + j], SCALE_INV, b2s[colg]);
                        add += __expf(lv);
                        if (colg == tcol4[s]) tk4[s] = lv;
                    }
                }
                s4[s] += add;
                if (nt == 0 && warp_n == 0 && qc == 0)
                    bl4[s] = fmaf(acc[mi][0][hf], SCALE_INV, b2s[0]);
            }
        }
    }

#pragma unroll
    for (int off = 1; off <= 2; off <<= 1) {
#pragma unroll
        for (int s = 0; s < 4; ++s) {
            s4[s] += __shfl_xor_sync(0xffffffffu, s4[s], off);
            tk4[s] = fmaxf(tk4[s], __shfl_xor_sync(0xffffffffu, tk4[s], off));
            bl4[s] = fmaxf(bl4[s], __shfl_xor_sync(0xffffffffu, bl4[s], off));
        }
    }
    if (qc == 0) {
#pragma unroll
        for (int s = 0; s < 4; ++s) {
            int r = rowloc[s];
            cs[warp_n][r] = s4[s];
            ctk[warp_n][r] = tk4[s];
            if (warp_n == 0) cbl[r] = bl4[s];
        }
    }
    __syncthreads();

    if (tid < MT) {
        int row = row0 + tid;
        if (row < ROWS_B) {
            float lse = __logf(cs[0][tid] + cs[1][tid] + cs[2][tid] + cs[3][tid]);
            float tk = fmaxf(fmaxf(ctk[0][tid], ctk[1][tid]),
                             fmaxf(ctk[2][tid], ctk[3][tid]));
            int t = row / U1, u = row - t * U1;
            g_blank[(b * Tc + t) * U1 + u] = cbl[tid] - lse;
            if (u < Uc) g_label[(b * Tc + t) * Uc + u] = tk - lse;
        }
    }
}

// ---------------------------------------------------------------------------
// Kernel 2: RNN-T forward DP. Block-wide wavefront (best measured structure)
// with (a) fast-math logaddexp off the serial chain's slow log1pf, and
// (b) next-diagonal lp loads prefetched before the barrier.
// The last block to finish also writes the final output (finalize folded in).
// ---------------------------------------------------------------------------
constexpr int DP_SMEM = (Tc * U1 + Tc * Uc) * (int)sizeof(float); // 160800

__global__ __launch_bounds__(128) void dp_kernel(
    const int* __restrict__ out_len, const int* __restrict__ tok_len,
    float* __restrict__ out) {
    extern __shared__ float lp[];
    float* blankS = lp;
    float* labelS = lp + Tc * U1;
    __shared__ float llk;

    const int b = blockIdx.x, tid = threadIdx.x;
    {
        const float4* src = (const float4*)(g_blank + (size_t)b * Tc * U1);
        float4* dst = (float4*)blankS;
        for (int i = tid; i < Tc * U1 / 4; i += 128) dst[i] = src[i];
        const float4* src2 = (const float4*)(g_label + (size_t)b * Tc * Uc);
        float4* dst2 = (float4*)labelS;
        for (int i = tid; i < Tc * Uc / 4; i += 128) dst2[i] = src2[i];
    }
    const int tl = out_len[b], ul = tok_len[b];
    __syncthreads();

    __shared__ float bufA[U1 + 2], bufB[U1 + 2];
    float* prev = bufA;
    float* cur = bufB;
    const int u = tid;
    const bool ok = (u <= Uc);

    float cbl = 0.f, clb = 0.f;   // lp values for current diagonal (prefetched)

    for (int d = 0; d <= (Tc - 1) + Uc; ++d) {
        // prefetch lp for diagonal d+1 (independent of alpha chain)
        float nbl = 0.f, nlb = 0.f;
        {
            int tn = (d + 1) - u;
            if (ok && tn >= 1 && tn < Tc) nbl = blankS[(tn - 1) * U1 + u];
            if (ok && u >= 1 && tn >= 0 && tn < Tc) nlb = labelS[tn * Uc + (u - 1)];
        }
        int t = d - u;
        if (ok && t >= 0 && t < Tc) {
            float val;
            if (d == 0) {
                val = 0.f;
            } else {
                float x = (t >= 1) ? prev[u] + cbl : -INFINITY;
                float y = (u >= 1) ? prev[u - 1] + clb : -INFINITY;
                float hi = fmaxf(x, y), lo = fminf(x, y);
                val = (lo == -INFINITY) ? hi : hi + __logf(1.f + __expf(lo - hi));
            }
            cur[u] = val;
            if (t == tl - 1 && u == ul) llk = val;
        }
        __syncthreads();
        float* tmp = prev; prev = cur; cur = tmp;
        cbl = nbl; clb = nlb;
    }

    if (tid == 0) {
        g_ll[b] = llk + blankS[(tl - 1) * U1 + ul];
        __threadfence();
        int old = atomicAdd(&g_done, 1);
        if (old == Bc - 1) {
            volatile float* ll = g_ll;
            out[0] = -0.25f * (ll[0] + ll[1] + ll[2] + ll[3]);
            g_done = 0;                 // reset for next (graph-replayed) launch
        }
    }
}

// ---------------------------------------------------------------------------
extern "C" void kernel_launch(void* const* d_in, const int* in_sizes, int n_in,
                              void* d_out, int out_size) {
    const float* enc     = (const float*)d_in[0];
    const float* dec     = (const float*)d_in[1];
    const int*   tokens  = (const int*)d_in[2];
    const int*   out_len = (const int*)d_in[3];
    const int*   tok_len = (const int*)d_in[4];
    const float* W1      = (const float*)d_in[5];
    const float* b1      = (const float*)d_in[6];
    const float* W2      = (const float*)d_in[7];
    const float* b2      = (const float*)d_in[8];
    float* out = (float*)d_out;

    cudaFuncSetAttribute(joint_mma, cudaFuncAttributeMaxDynamicSharedMemorySize, DSMEM);
    cudaFuncSetAttribute(dp_kernel, cudaFuncAttributeMaxDynamicSharedMemorySize, DP_SMEM);

    prep_kernel<<<PREP_BLKS, 256>>>(W2, enc, dec, W1, b1);
    joint_mma<<<Bc * BLKS_B, 256, DSMEM>>>(b2, tokens);
    dp_kernel<<<Bc, 128, DP_SMEM>>>(out_len, tok_len, out);
}